// round 11
// baseline (speedup 1.0000x reference)
#include <cuda_runtime.h>
#include <cuda_bf16.h>
#include <stdint.h>
#include <math.h>

#define CB 128
#define CS 128
#define CH 1024
#define CE 512
#define CV 32000

// ---------------- scratch (__device__ globals; no allocations allowed) -------
__device__ __align__(16) float g_hW[CB * CH];
__device__ __align__(16) float g_score[CB * CS];
__device__ __align__(16) float g_gates[CB * 4096];
__device__ __align__(16) __nv_bfloat16 g_xin_hi[CB * 2560];   // [emb|context|h_last]
__device__ __align__(16) __nv_bfloat16 g_xin_lo[CB * 2560];
__device__ __align__(16) __nv_bfloat16 g_out2_hi[CB * 2048];  // [h_new | context]
__device__ __align__(16) __nv_bfloat16 g_out2_lo[CB * 2048];
__device__ __align__(16) __nv_bfloat16 g_enc_hi[CB * CS * CH];
__device__ __align__(16) __nv_bfloat16 g_enc_lo[CB * CS * CH];
__device__ __align__(16) __nv_bfloat16 g_w2_hi[CH * CH];      // attn_W[:, H:2H] as [n][k]
__device__ __align__(16) __nv_bfloat16 g_w2_lo[CH * CH];

// ---------------- helpers ----------------------------------------------------
__device__ __forceinline__ void splitf(float x, __nv_bfloat16 &hi, __nv_bfloat16 &lo) {
    hi = __float2bfloat16_rn(x);
    lo = __float2bfloat16_rn(x - __bfloat162float(hi));
}
__device__ __forceinline__ float sigf(float x) { return 1.0f / (1.0f + expf(-x)); }
__device__ __forceinline__ uint32_t s2u(const void *p) {
    return (uint32_t)__cvta_generic_to_shared(p);
}
__device__ __forceinline__ void ldsm4(uint32_t &r0, uint32_t &r1, uint32_t &r2,
                                      uint32_t &r3, uint32_t addr) {
    asm volatile("ldmatrix.sync.aligned.m8n8.x4.shared.b16 {%0,%1,%2,%3}, [%4];"
                 : "=r"(r0), "=r"(r1), "=r"(r2), "=r"(r3)
                 : "r"(addr));
}

#define MMA16816(d, a0, a1, a2, a3, b0, b1)                                    \
    asm volatile(                                                              \
        "mma.sync.aligned.m16n8k16.row.col.f32.bf16.bf16.f32 "                 \
        "{%0,%1,%2,%3},{%4,%5,%6,%7},{%8,%9},{%0,%1,%2,%3};\n"                 \
        : "+f"(d[0]), "+f"(d[1]), "+f"(d[2]), "+f"(d[3])                       \
        : "r"(a0), "r"(a1), "r"(a2), "r"(a3), "r"(b0), "r"(b1))

#define CPASYNC16(dst, src)                                                    \
    asm volatile("cp.async.cg.shared.global [%0], [%1], 16;\n" ::"r"(dst),     \
                 "l"(src))
#define CPCOMMIT asm volatile("cp.async.commit_group;\n" ::)
#define CPWAIT1 asm volatile("cp.async.wait_group 1;\n" ::)
#define CPWAIT0 asm volatile("cp.async.wait_group 0;\n" ::)

// ---------------- precision split of encoder_outputs and attn_W[:,H:] --------
__global__ __launch_bounds__(256) void conv_enc_kernel(const float *__restrict__ enc) {
    size_t idx = (size_t)blockIdx.x * 256 + threadIdx.x;  // float4 index
    float4 v4 = ((const float4 *)enc)[idx];
    __nv_bfloat16 h0, h1, h2, h3, l0, l1, l2, l3;
    splitf(v4.x, h0, l0); splitf(v4.y, h1, l1);
    splitf(v4.z, h2, l2); splitf(v4.w, h3, l3);
    ((__nv_bfloat162 *)g_enc_hi)[idx * 2 + 0] = __halves2bfloat162(h0, h1);
    ((__nv_bfloat162 *)g_enc_hi)[idx * 2 + 1] = __halves2bfloat162(h2, h3);
    ((__nv_bfloat162 *)g_enc_lo)[idx * 2 + 0] = __halves2bfloat162(l0, l1);
    ((__nv_bfloat162 *)g_enc_lo)[idx * 2 + 1] = __halves2bfloat162(l2, l3);
}

// also zeroes g_score, seeds g_hW with attn_b, seeds g_gates with b_ih+b_hh
__global__ __launch_bounds__(256) void conv_w2_kernel(const float *__restrict__ attn_W,
                                                      const float *__restrict__ attn_b,
                                                      const float *__restrict__ b_ih,
                                                      const float *__restrict__ b_hh) {
    size_t idx = (size_t)blockIdx.x * 256 + threadIdx.x;  // float4 index, 262144 total
    if (blockIdx.x < 64) g_score[blockIdx.x * 256 + threadIdx.x] = 0.f;
    if (blockIdx.x < 512) {
        int i = blockIdx.x * 256 + threadIdx.x;  // 131072 floats of g_hW
        g_hW[i] = attn_b[i & (CH - 1)];
    }
    {
        int i2 = ((int)blockIdx.x * 256 + (int)threadIdx.x) * 2;  // 524288 floats
        g_gates[i2]     = b_ih[i2 & 4095] + b_hh[i2 & 4095];
        g_gates[i2 + 1] = b_ih[(i2 + 1) & 4095] + b_hh[(i2 + 1) & 4095];
    }
    int n = (int)(idx >> 8);
    int k = (int)(idx & 255) << 2;
    float4 v4 = *(const float4 *)(attn_W + (size_t)n * 2048 + 1024 + k);
    __nv_bfloat16 h0, h1, h2, h3, l0, l1, l2, l3;
    splitf(v4.x, h0, l0); splitf(v4.y, h1, l1);
    splitf(v4.z, h2, l2); splitf(v4.w, h3, l3);
    size_t o = ((size_t)n * CH + k) >> 1;
    ((__nv_bfloat162 *)g_w2_hi)[o + 0] = __halves2bfloat162(h0, h1);
    ((__nv_bfloat162 *)g_w2_hi)[o + 1] = __halves2bfloat162(h2, h3);
    ((__nv_bfloat162 *)g_w2_lo)[o + 0] = __halves2bfloat162(l0, l1);
    ((__nv_bfloat162 *)g_w2_lo)[o + 1] = __halves2bfloat162(l2, l3);
}

// ---------------- small GEMM: hW += hidden @ W1^T (K-split, atomic) ----------
__global__ __launch_bounds__(256) void hw_kernel(const float *__restrict__ hidden,
                                                 const float *__restrict__ attn_W) {
    __shared__ float Hs[128][65];
    __shared__ float Ws[16][65];
    const int tid = threadIdx.x;
    const int n0 = blockIdx.x * 16;
    const int kbase = blockIdx.y * 256;
    const int bt = tid & 63;
    const int nt = tid >> 6;
    float acc[2][4] = {{0.f, 0.f, 0.f, 0.f}, {0.f, 0.f, 0.f, 0.f}};

    for (int kc = 0; kc < 4; ++kc) {
        const int k0 = kbase + kc * 64;
#pragma unroll
        for (int i = 0; i < 8; ++i) {
            int idx = tid + 256 * i;
            int row = idx >> 4;
            int cv = (idx & 15) << 2;
            float4 v4 = *(const float4 *)(hidden + (size_t)row * CH + k0 + cv);
            Hs[row][cv] = v4.x; Hs[row][cv + 1] = v4.y;
            Hs[row][cv + 2] = v4.z; Hs[row][cv + 3] = v4.w;
        }
        {
            int row = tid >> 4;
            int cv = (tid & 15) << 2;
            float4 v4 = *(const float4 *)(attn_W + (size_t)(n0 + row) * 2048 + k0 + cv);
            Ws[row][cv] = v4.x; Ws[row][cv + 1] = v4.y;
            Ws[row][cv + 2] = v4.z; Ws[row][cv + 3] = v4.w;
        }
        __syncthreads();
#pragma unroll 8
        for (int k = 0; k < 64; ++k) {
            float w0 = Ws[nt * 4 + 0][k], w1 = Ws[nt * 4 + 1][k];
            float w2 = Ws[nt * 4 + 2][k], w3 = Ws[nt * 4 + 3][k];
            float h0 = Hs[bt * 2 + 0][k], h1 = Hs[bt * 2 + 1][k];
            acc[0][0] += h0 * w0; acc[0][1] += h0 * w1;
            acc[0][2] += h0 * w2; acc[0][3] += h0 * w3;
            acc[1][0] += h1 * w0; acc[1][1] += h1 * w1;
            acc[1][2] += h1 * w2; acc[1][3] += h1 * w3;
        }
        __syncthreads();
    }
#pragma unroll
    for (int i = 0; i < 2; ++i)
#pragma unroll
        for (int j = 0; j < 4; ++j) {
            int n = n0 + nt * 4 + j;
            atomicAdd(&g_hW[(size_t)(bt * 2 + i) * CH + n], acc[i][j]);
        }
}

// ---------------- pipelined bf16-split x3 GEMM: C = A@B^T (+bias / atomic) ---
// Used for the gates GEMM. A: pre-split bf16 hi/lo, cp.async 3 stages, ONE
// __syncthreads per k-tile. B: fp32, register-staged, split in-kernel.
// Tile 128 x 64 x 32. grid.x = N/64, grid.y = K-split chunk (kbase = y*K).
#define A2_STAGE (128 * 40)
#define B2_STAGE (64 * 40)
#define G2_SMEM_BYTES (3 * (A2_STAGE + B2_STAGE) * 2 * 2)

__global__ __launch_bounds__(256, 2) void gemm2_kernel(
    const __nv_bfloat16 *__restrict__ Ahi, const __nv_bfloat16 *__restrict__ Alo,
    int lda,
    const float *__restrict__ B1, int ldb1, int ksw,
    const float *__restrict__ B2, int ldb2,
    const float *__restrict__ bias1,
    float *__restrict__ C, int ldc, int K, int atomic_out) {
    extern __shared__ __align__(16) __nv_bfloat16 sm2[];
    __nv_bfloat16 *AsHi = sm2;                    // [3][A2_STAGE]
    __nv_bfloat16 *AsLo = AsHi + 3 * A2_STAGE;
    __nv_bfloat16 *BsHi = AsLo + 3 * A2_STAGE;    // [3][B2_STAGE]
    __nv_bfloat16 *BsLo = BsHi + 3 * B2_STAGE;

    const int tid = threadIdx.x;
    const int lane = tid & 31;
    const int gid = lane >> 2;
    const int t4 = lane & 3;
    const int wm = (tid >> 5) >> 1;
    const int wn = (tid >> 5) & 1;
    const int n0 = blockIdx.x * 64;
    const int kbase = blockIdx.y * K;

    const int a_mrow = (lane & 15);
    const int a_koff = (lane >> 4) << 3;
    const int b_nrow = (lane & 7) + ((lane >> 4) << 3);
    const int b_koff = ((lane >> 3) & 1) << 3;

    const int nk = K >> 5;

    float acc[2][4][4];
#pragma unroll
    for (int i = 0; i < 2; i++)
#pragma unroll
        for (int j = 0; j < 4; j++)
#pragma unroll
            for (int c = 0; c < 4; c++) acc[i][j][c] = 0.f;

    float4 breg[2];
    auto ldB = [&](int k0) {
#pragma unroll
        for (int i = 0; i < 2; ++i) {
            int idx = tid + i * 256;
            int row = n0 + (idx >> 3);
            int k = kbase + k0 + ((idx & 7) << 2);
            const float *src = (k < ksw) ? (B1 + (size_t)row * ldb1 + k)
                                         : (B2 + (size_t)row * ldb2 + (k - ksw));
            breg[i] = *(const float4 *)src;
        }
    };
    auto stB = [&](int st) {
#pragma unroll
        for (int i = 0; i < 2; ++i) {
            int idx = tid + i * 256;
            int row = idx >> 3;
            int col = (idx & 7) << 2;
            __nv_bfloat16 h0, h1, h2, h3, l0, l1, l2, l3;
            splitf(breg[i].x, h0, l0); splitf(breg[i].y, h1, l1);
            splitf(breg[i].z, h2, l2); splitf(breg[i].w, h3, l3);
            __nv_bfloat16 *dh = BsHi + st * B2_STAGE + row * 40 + col;
            __nv_bfloat16 *dl = BsLo + st * B2_STAGE + row * 40 + col;
            *(__nv_bfloat162 *)dh       = __halves2bfloat162(h0, h1);
            *(__nv_bfloat162 *)(dh + 2) = __halves2bfloat162(h2, h3);
            *(__nv_bfloat162 *)dl       = __halves2bfloat162(l0, l1);
            *(__nv_bfloat162 *)(dl + 2) = __halves2bfloat162(l2, l3);
        }
    };
    auto cpA = [&](int st, int k0) {
#pragma unroll
        for (int i = 0; i < 2; ++i) {
            int idx = tid + i * 256;
            int row = idx >> 2;
            int col = (idx & 3) << 3;
            uint32_t dof = st * A2_STAGE + row * 40 + col;
            size_t go = (size_t)row * lda + kbase + k0 + col;
            CPASYNC16(s2u(AsHi + dof), Ahi + go);
            CPASYNC16(s2u(AsLo + dof), Alo + go);
        }
        CPCOMMIT;
    };

    cpA(0, 0);
    if (nk > 1) cpA(1, 32);
    ldB(0);
    stB(0);
    if (nk > 1) ldB(32);

    for (int kt = 0; kt < nk; ++kt) {
        if (kt < nk - 1) { CPWAIT1; } else { CPWAIT0; }
        __syncthreads();  // single barrier: publishes stage kt, frees stage kt+2
        if (kt + 1 < nk) stB((kt + 1) % 3);
        if (kt + 2 < nk) {
            ldB((kt + 2) * 32);
            cpA((kt + 2) % 3, (kt + 2) * 32);
        }
        const int st = kt % 3;
        const __nv_bfloat16 *cAH = AsHi + st * A2_STAGE;
        const __nv_bfloat16 *cAL = AsLo + st * A2_STAGE;
        const __nv_bfloat16 *cBH = BsHi + st * B2_STAGE;
        const __nv_bfloat16 *cBL = BsLo + st * B2_STAGE;
#pragma unroll
        for (int kk = 0; kk < 32; kk += 16) {
            uint32_t ah[2][4], al[2][4];
#pragma unroll
            for (int fm = 0; fm < 2; ++fm) {
                int rowb = wm * 32 + fm * 16 + a_mrow;
                ldsm4(ah[fm][0], ah[fm][1], ah[fm][2], ah[fm][3],
                      s2u(cAH + rowb * 40 + kk + a_koff));
                ldsm4(al[fm][0], al[fm][1], al[fm][2], al[fm][3],
                      s2u(cAL + rowb * 40 + kk + a_koff));
            }
#pragma unroll
            for (int fnp = 0; fnp < 2; ++fnp) {
                uint32_t bh[4], bl[4];
                int nrow = wn * 32 + fnp * 16 + b_nrow;
                ldsm4(bh[0], bh[1], bh[2], bh[3],
                      s2u(cBH + nrow * 40 + kk + b_koff));
                ldsm4(bl[0], bl[1], bl[2], bl[3],
                      s2u(cBL + nrow * 40 + kk + b_koff));
#pragma unroll
                for (int fm = 0; fm < 2; ++fm) {
                    float *d0 = acc[fm][fnp * 2];
                    float *d1 = acc[fm][fnp * 2 + 1];
                    MMA16816(d0, ah[fm][0], ah[fm][1], ah[fm][2], ah[fm][3], bh[0], bh[1]);
                    MMA16816(d0, ah[fm][0], ah[fm][1], ah[fm][2], ah[fm][3], bl[0], bl[1]);
                    MMA16816(d0, al[fm][0], al[fm][1], al[fm][2], al[fm][3], bh[0], bh[1]);
                    MMA16816(d1, ah[fm][0], ah[fm][1], ah[fm][2], ah[fm][3], bh[2], bh[3]);
                    MMA16816(d1, ah[fm][0], ah[fm][1], ah[fm][2], ah[fm][3], bl[2], bl[3]);
                    MMA16816(d1, al[fm][0], al[fm][1], al[fm][2], al[fm][3], bh[2], bh[3]);
                }
            }
        }
    }
#pragma unroll
    for (int fm = 0; fm < 2; ++fm)
#pragma unroll
        for (int fn = 0; fn < 4; ++fn) {
            int row = wm * 32 + fm * 16 + gid;
            int col = n0 + wn * 32 + fn * 8 + (t4 << 1);
            if (atomic_out) {
                atomicAdd(&C[(size_t)row * ldc + col], acc[fm][fn][0]);
                atomicAdd(&C[(size_t)row * ldc + col + 1], acc[fm][fn][1]);
                atomicAdd(&C[(size_t)(row + 8) * ldc + col], acc[fm][fn][2]);
                atomicAdd(&C[(size_t)(row + 8) * ldc + col + 1], acc[fm][fn][3]);
            } else {
                float b0 = bias1 ? bias1[col] : 0.f;
                float b1 = bias1 ? bias1[col + 1] : 0.f;
                C[(size_t)row * ldc + col]           = acc[fm][fn][0] + b0;
                C[(size_t)row * ldc + col + 1]       = acc[fm][fn][1] + b1;
                C[(size_t)(row + 8) * ldc + col]     = acc[fm][fn][2] + b0;
                C[(size_t)(row + 8) * ldc + col + 1] = acc[fm][fn][3] + b1;
            }
        }
}

// ---------------- FC GEMM: logits = out2 @ fc_W^T + fc_b ---------------------
// attn-style shape: tile 128(M) x 128(N) x 32(K), swizzled 64B rows, 3-stage
// cp.async for A (bf16 pre-split), fp32 B register-staged + split to smem.
// grid = 250 CTAs (single wave at 2 CTA/SM).
#define FC_STAGE_B 32768
#define FC_SMEM_BYTES (3 * FC_STAGE_B)

__global__ __launch_bounds__(256, 2) void fc_kernel(
    const __nv_bfloat16 *__restrict__ Ahi, const __nv_bfloat16 *__restrict__ Alo,
    const float *__restrict__ B, const float *__restrict__ bias,
    float *__restrict__ C) {
    extern __shared__ __align__(16) char smem[];
    const uint32_t sb = s2u(smem);

    const int tid = threadIdx.x;
    const int lane = tid & 31;
    const int gid = lane >> 2;
    const int t4 = lane & 3;
    const int wm = (tid >> 5) >> 1;  // 0..3
    const int wn = (tid >> 5) & 1;   // 0..1
    const int n0 = blockIdx.x * 128;

    const int a_mrow = (lane & 15);
    const int a_ch = lane >> 4;
    const int b_nrow = (lane & 7) + ((lane >> 4) << 3);
    const int b_ch = (lane >> 3) & 1;

    float acc[2][8][4];
#pragma unroll
    for (int i = 0; i < 2; i++)
#pragma unroll
        for (int j = 0; j < 8; j++)
#pragma unroll
            for (int c = 0; c < 4; c++) acc[i][j][c] = 0.f;

    float4 breg[4];
    auto ldB = [&](int k0) {
#pragma unroll
        for (int i = 0; i < 4; ++i) {
            int idx = tid + i * 256;
            int row = n0 + (idx >> 3);
            int col = (idx & 7) << 2;
            breg[i] = *(const float4 *)(B + (size_t)row * 2048 + k0 + col);
        }
    };
    auto stB = [&](int st) {
#pragma unroll
        for (int i = 0; i < 4; ++i) {
            int idx = tid + i * 256;
            int row = idx >> 3;            // 0..127
            int colf = (idx & 7) << 2;     // fp32 col 0..28
            int boff = colf * 2;           // byte offset in 64B row
            int ch = boff >> 4;
            int inner = boff & 15;
            uint32_t off = (uint32_t)st * FC_STAGE_B + 16384 + row * 64 +
                           ((uint32_t)(ch ^ ((row >> 1) & 3)) << 4) + inner;
            __nv_bfloat16 h0, h1, h2, h3, l0, l1, l2, l3;
            splitf(breg[i].x, h0, l0); splitf(breg[i].y, h1, l1);
            splitf(breg[i].z, h2, l2); splitf(breg[i].w, h3, l3);
            *(__nv_bfloat162 *)(smem + off)        = __halves2bfloat162(h0, h1);
            *(__nv_bfloat162 *)(smem + off + 4)    = __halves2bfloat162(h2, h3);
            *(__nv_bfloat162 *)(smem + off + 8192) = __halves2bfloat162(l0, l1);
            *(__nv_bfloat162 *)(smem + off + 8196) = __halves2bfloat162(l2, l3);
        }
    };
    auto cpA = [&](int st, int k0) {
#pragma unroll
        for (int i = 0; i < 2; ++i) {
            int idx = tid + i * 256;
            int row = idx >> 2;
            int ch = idx & 3;
            uint32_t so = (uint32_t)st * FC_STAGE_B + row * 64 +
                          ((uint32_t)(ch ^ ((row >> 1) & 3)) << 4);
            size_t go = (size_t)row * 2048 + k0 + ch * 8;
            CPASYNC16(sb + so, Ahi + go);
            CPASYNC16(sb + 8192 + so, Alo + go);
        }
        CPCOMMIT;
    };

    cpA(0, 0);
    cpA(1, 32);
    ldB(0);
    stB(0);
    ldB(32);

    const int nk = 2048 / 32;  // 64
    for (int kt = 0; kt < nk; ++kt) {
        if (kt < nk - 1) { CPWAIT1; } else { CPWAIT0; }
        __syncthreads();
        if (kt + 1 < nk) stB((kt + 1) % 3);
        if (kt + 2 < nk) {
            ldB((kt + 2) * 32);
            cpA((kt + 2) % 3, (kt + 2) * 32);
        }
        const uint32_t csb = sb + (uint32_t)(kt % 3) * FC_STAGE_B;
#pragma unroll
        for (int kk = 0; kk < 32; kk += 16) {
            uint32_t ah[2][4], al[2][4];
#pragma unroll
            for (int fm = 0; fm < 2; ++fm) {
                int rowb = wm * 32 + fm * 16 + a_mrow;
                uint32_t sw = (uint32_t)(((kk >> 3) + a_ch) ^ ((rowb >> 1) & 3));
                uint32_t ad = csb + rowb * 64 + (sw << 4);
                ldsm4(ah[fm][0], ah[fm][1], ah[fm][2], ah[fm][3], ad);
                ldsm4(al[fm][0], al[fm][1], al[fm][2], al[fm][3], ad + 8192);
            }
#pragma unroll
            for (int fnp = 0; fnp < 4; ++fnp) {
                uint32_t bh[4], bl[4];
                int nrow = wn * 64 + fnp * 16 + b_nrow;
                uint32_t sw = (uint32_t)(((kk >> 3) + b_ch) ^ ((nrow >> 1) & 3));
                uint32_t bd = csb + 16384 + nrow * 64 + (sw << 4);
                ldsm4(bh[0], bh[1], bh[2], bh[3], bd);
                ldsm4(bl[0], bl[1], bl[2], bl[3], bd + 8192);
#pragma unroll
                for (int fm = 0; fm < 2; ++fm) {
                    float *d0 = acc[fm][fnp * 2];
                    float *d1 = acc[fm][fnp * 2 + 1];
                    MMA16816(d0, ah[fm][0], ah[fm][1], ah[fm][2], ah[fm][3], bh[0], bh[1]);
                    MMA16816(d0, ah[fm][0], ah[fm][1], ah[fm][2], ah[fm][3], bl[0], bl[1]);
                    MMA16816(d0, al[fm][0], al[fm][1], al[fm][2], al[fm][3], bh[0], bh[1]);
                    MMA16816(d1, ah[fm][0], ah[fm][1], ah[fm][2], ah[fm][3], bh[2], bh[3]);
                    MMA16816(d1, ah[fm][0], ah[fm][1], ah[fm][2], ah[fm][3], bl[2], bl[3]);
                    MMA16816(d1, al[fm][0], al[fm][1], al[fm][2], al[fm][3], bh[2], bh[3]);
                }
            }
        }
    }
#pragma unroll
    for (int fm = 0; fm < 2; ++fm)
#pragma unroll
        for (int fn = 0; fn < 8; ++fn) {
            int row = wm * 32 + fm * 16 + gid;
            int col = n0 + wn * 64 + fn * 8 + (t4 << 1);
            float b0 = bias[col], b1 = bias[col + 1];
            C[(size_t)row * CV + col]           = acc[fm][fn][0] + b0;
            C[(size_t)row * CV + col + 1]       = acc[fm][fn][1] + b1;
            C[(size_t)(row + 8) * CV + col]     = acc[fm][fn][2] + b0;
            C[(size_t)(row + 8) * CV + col + 1] = acc[fm][fn][3] + b1;
        }
}

// ---------------- fused energy GEMM + tanh + v-dot -> score[B,S] -------------
// Tile 64(M) x 128(N) x 1024(K). Grid (8, 256): x = n-chunk of 128,
// y = m-tile (b = y>>1, 64-row half = y&1). 2048 tiles -> ~1% wave tail.
// 8 warps: wm = wid&1 (2 x 32 m-rows), wn = wid>>1 (4 x 32 n-cols).
// 3-stage cp.async, ONE barrier per k-tile, swizzled 64B rows.
// Per-stage layout (bytes): AsHi @0 (4K), AsLo @4096, BsHi @8192 (8K), BsLo @16384.
#define AT_STAGE_B 24576
#define ATTN_SMEM_BYTES (3 * AT_STAGE_B + 256)

__global__ __launch_bounds__(256, 2) void attn_score_kernel(const float *__restrict__ v) {
    extern __shared__ __align__(16) char smem[];
    const uint32_t sb = s2u(smem);
    float *red = (float *)(smem + 3 * AT_STAGE_B);

    const int tid = threadIdx.x;
    const int lane = tid & 31;
    const int wid = tid >> 5;
    const int gid = lane >> 2;
    const int t4 = lane & 3;
    const int wm = wid & 1;    // 0..1 (m tile of 32)
    const int wn = wid >> 1;   // 0..3 (n tile of 32)
    const int b = blockIdx.y >> 1;
    const int mh = blockIdx.y & 1;
    const int mbase = b * 128 + mh * 64;
    const int n0 = blockIdx.x * 128;
    if (tid < 64) red[tid] = 0.f;

    const int a_mrow = (lane & 15);
    const int a_ch = lane >> 4;
    const int b_nrow = (lane & 7) + ((lane >> 4) << 3);
    const int b_ch = (lane >> 3) & 1;

    float acc[2][4][4];
#pragma unroll
    for (int i = 0; i < 2; i++)
#pragma unroll
        for (int j = 0; j < 4; j++)
#pragma unroll
            for (int c = 0; c < 4; c++) acc[i][j][c] = 0.f;

#define LOAD_STAGE(st, k0)                                                     \
    do {                                                                       \
        {                                                                      \
            int row = tid >> 2;  /* 0..63 */                                   \
            int ch = tid & 3;                                                  \
            uint32_t so = (uint32_t)(st) * AT_STAGE_B + row * 64 +             \
                          ((uint32_t)(ch ^ ((row >> 1) & 3)) << 4);            \
            size_t goA = (size_t)(mbase + row) * CH + (k0) + ch * 8;           \
            CPASYNC16(sb + so, g_enc_hi + goA);                                \
            CPASYNC16(sb + 4096 + so, g_enc_lo + goA);                         \
        }                                                                      \
        _Pragma("unroll") for (int i = 0; i < 2; ++i) {                        \
            int idx = tid + i * 256;                                           \
            int row = idx >> 2;  /* 0..127 */                                  \
            int ch = idx & 3;                                                  \
            uint32_t so = (uint32_t)(st) * AT_STAGE_B + 8192 + row * 64 +      \
                          ((uint32_t)(ch ^ ((row >> 1) & 3)) << 4);            \
            size_t goB = (size_t)(n0 + row) * CH + (k0) + ch * 8;              \
            CPASYNC16(sb + so, g_w2_hi + goB);                                 \
            CPASYNC16(sb + 8192 + so, g_w2_lo + goB);                          \
        }                                                                      \
        CPCOMMIT;                                                              \
    } while (0)

    LOAD_STAGE(0, 0);
    LOAD_STAGE(1, 32);
    for (int kt = 0; kt < 32; ++kt) {
        if (kt < 31) { CPWAIT1; } else { CPWAIT0; }
        __syncthreads();  // single barrier: publishes stage kt, frees stage kt+2
        if (kt + 2 < 32) LOAD_STAGE((kt + 2) % 3, (kt + 2) * 32);
        const uint32_t csb = sb + (uint32_t)(kt % 3) * AT_STAGE_B;
#pragma unroll
        for (int kk = 0; kk < 32; kk += 16) {
            uint32_t ah[2][4], al[2][4];
#pragma unroll
            for (int fm = 0; fm < 2; ++fm) {
                int rowb = wm * 32 + fm * 16 + a_mrow;
                uint32_t sw = (uint32_t)(((kk >> 3) + a_ch) ^ ((rowb >> 1) & 3));
                uint32_t ad = csb + rowb * 64 + (sw << 4);
                ldsm4(ah[fm][0], ah[fm][1], ah[fm][2], ah[fm][3], ad);
                ldsm4(al[fm][0], al[fm][1], al[fm][2], al[fm][3], ad + 4096);
            }
#pragma unroll
            for (int fnp = 0; fnp < 2; ++fnp) {
                uint32_t bh[4], bl[4];
                int nrow = wn * 32 + fnp * 16 + b_nrow;
                uint32_t sw = (uint32_t)(((kk >> 3) + b_ch) ^ ((nrow >> 1) & 3));
                uint32_t bd = csb + 8192 + nrow * 64 + (sw << 4);
                ldsm4(bh[0], bh[1], bh[2], bh[3], bd);
                ldsm4(bl[0], bl[1], bl[2], bl[3], bd + 8192);
#pragma unroll
                for (int fm = 0; fm < 2; ++fm) {
                    float *d0 = acc[fm][fnp * 2];
                    float *d1 = acc[fm][fnp * 2 + 1];
                    MMA16816(d0, ah[fm][0], ah[fm][1], ah[fm][2], ah[fm][3], bh[0], bh[1]);
                    MMA16816(d0, ah[fm][0], ah[fm][1], ah[fm][2], ah[fm][3], bl[0], bl[1]);
                    MMA16816(d0, al[fm][0], al[fm][1], al[fm][2], al[fm][3], bh[0], bh[1]);
                    MMA16816(d1, ah[fm][0], ah[fm][1], ah[fm][2], ah[fm][3], bh[2], bh[3]);
                    MMA16816(d1, ah[fm][0], ah[fm][1], ah[fm][2], ah[fm][3], bl[2], bl[3]);
                    MMA16816(d1, al[fm][0], al[fm][1], al[fm][2], al[fm][3], bh[2], bh[3]);
                }
            }
        }
    }
    __syncthreads();

    const float *hWb = g_hW + (size_t)b * CH;
    float pA[2] = {0.f, 0.f}, pB[2] = {0.f, 0.f};
#pragma unroll
    for (int fm = 0; fm < 2; ++fm)
#pragma unroll
        for (int fn = 0; fn < 4; ++fn) {
            int col = n0 + wn * 32 + fn * 8 + (t4 << 1);
            float hw0 = hWb[col], hw1 = hWb[col + 1];
            float v0 = v[col], v1 = v[col + 1];
            pA[fm] += tanhf(acc[fm][fn][0] + hw0) * v0 +
                      tanhf(acc[fm][fn][1] + hw1) * v1;
            pB[fm] += tanhf(acc[fm][fn][2] + hw0) * v0 +
                      tanhf(acc[fm][fn][3] + hw1) * v1;
        }
#pragma unroll
    for (int fm = 0; fm < 2; ++fm)
#pragma unroll
        for (int j = 0; j < 2; ++j) {
            float val = j ? pB[fm] : pA[fm];
            val += __shfl_xor_sync(0xffffffffu, val, 1);
            val += __shfl_xor_sync(0xffffffffu, val, 2);
            if (t4 == 0) atomicAdd(&red[wm * 32 + fm * 16 + j * 8 + gid], val);
        }
    __syncthreads();
    if (tid < 64) atomicAdd(&g_score[b * 128 + mh * 64 + tid], red[tid]);
}

// ---------------- softmax over S, writes attn output + weights in place ------
__global__ __launch_bounds__(128) void softmax_kernel(float *__restrict__ out_attn) {
    const int b = blockIdx.x;
    const int t = threadIdx.x;
    __shared__ float sm[128];
    float s = g_score[b * 128 + t];
    sm[t] = s;
    __syncthreads();
#pragma unroll
    for (int st = 64; st > 0; st >>= 1) {
        if (t < st) sm[t] = fmaxf(sm[t], sm[t + st]);
        __syncthreads();
    }
    float mx = sm[0];
    __syncthreads();
    float e = expf(s - mx);
    sm[t] = e;
    __syncthreads();
#pragma unroll
    for (int st = 64; st > 0; st >>= 1) {
        if (t < st) sm[t] += sm[t + st];
        __syncthreads();
    }
    float w = e / sm[0];
    g_score[b * 128 + t] = w;
    out_attn[b * 128 + t] = w;
}

// ---------------- context + assemble xin (grid (128,4): H split by 4) --------
__global__ __launch_bounds__(256) void context_kernel(
    const int *__restrict__ x, const float *__restrict__ emb_table,
    const float *__restrict__ hidden, const float *__restrict__ enc) {
    const int b = blockIdx.x;
    const int q = blockIdx.y;
    const int t = threadIdx.x;
    __shared__ float w_s[128];
    if (t < 128) w_s[t] = g_score[b * 128 + t];
    const int h = q * 256 + t;
    if (q < 2) {
        int i = q * 256 + t;
        __nv_bfloat16 hi, lo;
        splitf(emb_table[(size_t)x[b] * CE + i], hi, lo);
        g_xin_hi[(size_t)b * 2560 + i] = hi;
        g_xin_lo[(size_t)b * 2560 + i] = lo;
    }
    {
        __nv_bfloat16 hi, lo;
        splitf(hidden[(size_t)b * CH + h], hi, lo);
        g_xin_hi[(size_t)b * 2560 + 1536 + h] = hi;
        g_xin_lo[(size_t)b * 2560 + 1536 + h] = lo;
    }
    __syncthreads();
    float acc = 0.f;
    const float *encb = enc + (size_t)b * CS * CH + h;
#pragma unroll 8
    for (int s = 0; s < CS; ++s) acc += w_s[s] * encb[(size_t)s * CH];
    __nv_bfloat16 hi, lo;
    splitf(acc, hi, lo);
    g_xin_hi[(size_t)b * 2560 + 512 + h] = hi;
    g_xin_lo[(size_t)b * 2560 + 512 + h] = lo;
    g_out2_hi[(size_t)b * 2048 + 1024 + h] = hi;
    g_out2_lo[(size_t)b * 2048 + 1024 + h] = lo;
}

// ---------------- LSTM pointwise ---------------------------------------------
__global__ __launch_bounds__(256) void lstm_kernel(
    const float *__restrict__ cell, float *__restrict__ out_h,
    float *__restrict__ out_c) {
    int id = blockIdx.x * 256 + threadIdx.x;
    int b = id >> 10;
    int h = id & 1023;
    const float *gt = g_gates + (size_t)b * 4096;
    float gi = gt[h], gf = gt[1024 + h], gg = gt[2048 + h], go = gt[3072 + h];
    float c_old = cell[(size_t)b * CH + h];
    float cn = sigf(gf) * c_old + sigf(gi) * tanhf(gg);
    float hn = sigf(go) * tanhf(cn);
    out_h[(size_t)b * CH + h] = hn;
    out_c[(size_t)b * CH + h] = cn;
    __nv_bfloat16 hi, lo;
    splitf(hn, hi, lo);
    g_out2_hi[(size_t)b * 2048 + h] = hi;
    g_out2_lo[(size_t)b * 2048 + h] = lo;
}

// ---------------- launch ------------------------------------------------------
extern "C" void kernel_launch(void *const *d_in, const int *in_sizes, int n_in,
                              void *d_out, int out_size) {
    (void)in_sizes; (void)n_in; (void)out_size;
    const int *x           = (const int *)d_in[0];
    const float *hidden    = (const float *)d_in[1];
    const float *cell      = (const float *)d_in[2];
    const float *enc       = (const float *)d_in[3];
    const float *emb_table = (const float *)d_in[4];
    const float *attn_W    = (const float *)d_in[5];
    const float *attn_b    = (const float *)d_in[6];
    const float *v         = (const float *)d_in[7];
    const float *W_ih      = (const float *)d_in[8];
    const float *W_hh      = (const float *)d_in[9];
    const float *b_ih      = (const float *)d_in[10];
    const float *b_hh      = (const float *)d_in[11];
    const float *fc_W      = (const float *)d_in[12];
    const float *fc_b      = (const float *)d_in[13];

    float *out        = (float *)d_out;
    float *out_logits = out;
    float *out_h      = out + (size_t)CB * CV;
    float *out_c      = out_h + (size_t)CB * CH;
    float *out_attn   = out_c + (size_t)CB * CH;

    float *gatesp = nullptr;
    __nv_bfloat16 *o2h = nullptr, *o2l = nullptr, *xih = nullptr, *xil = nullptr;
    cudaGetSymbolAddress((void **)&gatesp, g_gates);
    cudaGetSymbolAddress((void **)&o2h, g_out2_hi);
    cudaGetSymbolAddress((void **)&o2l, g_out2_lo);
    cudaGetSymbolAddress((void **)&xih, g_xin_hi);
    cudaGetSymbolAddress((void **)&xil, g_xin_lo);

    cudaFuncSetAttribute(attn_score_kernel,
                         cudaFuncAttributeMaxDynamicSharedMemorySize,
                         ATTN_SMEM_BYTES);
    cudaFuncSetAttribute(gemm2_kernel,
                         cudaFuncAttributeMaxDynamicSharedMemorySize,
                         G2_SMEM_BYTES);
    cudaFuncSetAttribute(fc_kernel,
                         cudaFuncAttributeMaxDynamicSharedMemorySize,
                         FC_SMEM_BYTES);

    // 1) precision-split encoder_outputs
    conv_enc_kernel<<<16384, 256>>>(enc);
    // 2) split attn_W[:, H:2H] + zero score + seed g_hW, g_gates with biases
    conv_w2_kernel<<<1024, 256>>>(attn_W, attn_b, b_ih, b_hh);
    // 3) hW += h_last @ attn_W[:, :H]^T  (K-split x4, atomic)
    hw_kernel<<<dim3(64, 4), 256>>>(hidden, attn_W);
    // 4) fused energy GEMM + tanh + v-dot -> g_score  (launch #4: profiled)
    attn_score_kernel<<<dim3(8, 256), 256, ATTN_SMEM_BYTES>>>(v);
    // 5) softmax -> attn_weights output
    softmax_kernel<<<CB, 128>>>(out_attn);
    // 6) context + xin assembly (H split over 4 CTAs per batch)
    context_kernel<<<dim3(CB, 4), 256>>>(x, emb_table, hidden, enc);
    // 7) gates += xin @ [W_ih|W_hh]^T  (single launch, K-split via grid.y)
    gemm2_kernel<<<dim3(4096 / 64, 4), 256, G2_SMEM_BYTES>>>(
        xih, xil, 2560,
        W_ih, 1536, 1536, W_hh, CH,
        nullptr, gatesp, 4096, 640, 1);
    // 8) LSTM pointwise
    lstm_kernel<<<(CB * CH) / 256, 256>>>(cell, out_h, out_c);
    // 9) logits = [h_new|context] @ fc_W^T + fc_b  (128-wide attn-style tile)
    fc_kernel<<<CV / 128, 256, FC_SMEM_BYTES>>>(o2h, o2l, fc_W, fc_b, out_logits);
}

// round 12
// speedup vs baseline: 1.0525x; 1.0525x over previous
#include <cuda_runtime.h>
#include <cuda_bf16.h>
#include <stdint.h>
#include <math.h>

#define CB 128
#define CS 128
#define CH 1024
#define CE 512
#define CV 32000

// ---------------- scratch (__device__ globals; no allocations allowed) -------
__device__ __align__(16) float g_hW[CB * CH];
__device__ __align__(16) float g_score[CB * CS];   // raw scores (softmax done in context)
__device__ __align__(16) float g_gates[CB * 4096];
__device__ __align__(16) __nv_bfloat16 g_xin_hi[CB * 2560];   // [emb|context|h_last]
__device__ __align__(16) __nv_bfloat16 g_xin_lo[CB * 2560];
__device__ __align__(16) __nv_bfloat16 g_out2_hi[CB * 2048];  // [h_new | context]
__device__ __align__(16) __nv_bfloat16 g_out2_lo[CB * 2048];
__device__ __align__(16) __nv_bfloat16 g_enc_hi[CB * CS * CH];
__device__ __align__(16) __nv_bfloat16 g_enc_lo[CB * CS * CH];
__device__ __align__(16) __nv_bfloat16 g_w2_hi[CH * CH];      // attn_W[:, H:2H] as [n][k]
__device__ __align__(16) __nv_bfloat16 g_w2_lo[CH * CH];

// ---------------- helpers ----------------------------------------------------
__device__ __forceinline__ void splitf(float x, __nv_bfloat16 &hi, __nv_bfloat16 &lo) {
    hi = __float2bfloat16_rn(x);
    lo = __float2bfloat16_rn(x - __bfloat162float(hi));
}
__device__ __forceinline__ float sigf(float x) { return 1.0f / (1.0f + expf(-x)); }
__device__ __forceinline__ uint32_t s2u(const void *p) {
    return (uint32_t)__cvta_generic_to_shared(p);
}
__device__ __forceinline__ void ldsm4(uint32_t &r0, uint32_t &r1, uint32_t &r2,
                                      uint32_t &r3, uint32_t addr) {
    asm volatile("ldmatrix.sync.aligned.m8n8.x4.shared.b16 {%0,%1,%2,%3}, [%4];"
                 : "=r"(r0), "=r"(r1), "=r"(r2), "=r"(r3)
                 : "r"(addr));
}

#define MMA16816(d, a0, a1, a2, a3, b0, b1)                                    \
    asm volatile(                                                              \
        "mma.sync.aligned.m16n8k16.row.col.f32.bf16.bf16.f32 "                 \
        "{%0,%1,%2,%3},{%4,%5,%6,%7},{%8,%9},{%0,%1,%2,%3};\n"                 \
        : "+f"(d[0]), "+f"(d[1]), "+f"(d[2]), "+f"(d[3])                       \
        : "r"(a0), "r"(a1), "r"(a2), "r"(a3), "r"(b0), "r"(b1))

#define CPASYNC16(dst, src)                                                    \
    asm volatile("cp.async.cg.shared.global [%0], [%1], 16;\n" ::"r"(dst),     \
                 "l"(src))
#define CPCOMMIT asm volatile("cp.async.commit_group;\n" ::)
#define CPWAIT1 asm volatile("cp.async.wait_group 1;\n" ::)
#define CPWAIT0 asm volatile("cp.async.wait_group 0;\n" ::)

// ---------------- merged precision split + init ------------------------------
// grid 16384: all blocks split enc; blocks < 1024 also split attn_W[:,H:2H],
// zero g_score, seed g_hW with attn_b, seed g_gates with b_ih + b_hh.
__global__ __launch_bounds__(256) void conv_all_kernel(
    const float *__restrict__ enc, const float *__restrict__ attn_W,
    const float *__restrict__ attn_b, const float *__restrict__ b_ih,
    const float *__restrict__ b_hh) {
    size_t idx = (size_t)blockIdx.x * 256 + threadIdx.x;  // float4 index over enc
    float4 v4 = ((const float4 *)enc)[idx];
    __nv_bfloat16 h0, h1, h2, h3, l0, l1, l2, l3;
    splitf(v4.x, h0, l0); splitf(v4.y, h1, l1);
    splitf(v4.z, h2, l2); splitf(v4.w, h3, l3);
    ((__nv_bfloat162 *)g_enc_hi)[idx * 2 + 0] = __halves2bfloat162(h0, h1);
    ((__nv_bfloat162 *)g_enc_hi)[idx * 2 + 1] = __halves2bfloat162(h2, h3);
    ((__nv_bfloat162 *)g_enc_lo)[idx * 2 + 0] = __halves2bfloat162(l0, l1);
    ((__nv_bfloat162 *)g_enc_lo)[idx * 2 + 1] = __halves2bfloat162(l2, l3);

    if (blockIdx.x >= 1024) return;
    size_t idx2 = (size_t)blockIdx.x * 256 + threadIdx.x;  // 262144 float4s of w2
    if (blockIdx.x < 64) g_score[blockIdx.x * 256 + threadIdx.x] = 0.f;
    if (blockIdx.x < 512) {
        int i = blockIdx.x * 256 + threadIdx.x;
        g_hW[i] = attn_b[i & (CH - 1)];
    }
    {
        int i2 = ((int)blockIdx.x * 256 + (int)threadIdx.x) * 2;
        g_gates[i2]     = b_ih[i2 & 4095] + b_hh[i2 & 4095];
        g_gates[i2 + 1] = b_ih[(i2 + 1) & 4095] + b_hh[(i2 + 1) & 4095];
    }
    int n = (int)(idx2 >> 8);
    int k = (int)(idx2 & 255) << 2;
    float4 w4 = *(const float4 *)(attn_W + (size_t)n * 2048 + 1024 + k);
    splitf(w4.x, h0, l0); splitf(w4.y, h1, l1);
    splitf(w4.z, h2, l2); splitf(w4.w, h3, l3);
    size_t o = ((size_t)n * CH + k) >> 1;
    ((__nv_bfloat162 *)g_w2_hi)[o + 0] = __halves2bfloat162(h0, h1);
    ((__nv_bfloat162 *)g_w2_hi)[o + 1] = __halves2bfloat162(h2, h3);
    ((__nv_bfloat162 *)g_w2_lo)[o + 0] = __halves2bfloat162(l0, l1);
    ((__nv_bfloat162 *)g_w2_lo)[o + 1] = __halves2bfloat162(l2, l3);
}

// ---------------- small GEMM: hW += hidden @ W1^T (K-split, atomic) ----------
__global__ __launch_bounds__(256) void hw_kernel(const float *__restrict__ hidden,
                                                 const float *__restrict__ attn_W) {
    __shared__ float Hs[128][65];
    __shared__ float Ws[16][65];
    const int tid = threadIdx.x;
    const int n0 = blockIdx.x * 16;
    const int kbase = blockIdx.y * 256;
    const int bt = tid & 63;
    const int nt = tid >> 6;
    float acc[2][4] = {{0.f, 0.f, 0.f, 0.f}, {0.f, 0.f, 0.f, 0.f}};

    for (int kc = 0; kc < 4; ++kc) {
        const int k0 = kbase + kc * 64;
#pragma unroll
        for (int i = 0; i < 8; ++i) {
            int idx = tid + 256 * i;
            int row = idx >> 4;
            int cv = (idx & 15) << 2;
            float4 v4 = *(const float4 *)(hidden + (size_t)row * CH + k0 + cv);
            Hs[row][cv] = v4.x; Hs[row][cv + 1] = v4.y;
            Hs[row][cv + 2] = v4.z; Hs[row][cv + 3] = v4.w;
        }
        {
            int row = tid >> 4;
            int cv = (tid & 15) << 2;
            float4 v4 = *(const float4 *)(attn_W + (size_t)(n0 + row) * 2048 + k0 + cv);
            Ws[row][cv] = v4.x; Ws[row][cv + 1] = v4.y;
            Ws[row][cv + 2] = v4.z; Ws[row][cv + 3] = v4.w;
        }
        __syncthreads();
#pragma unroll 8
        for (int k = 0; k < 64; ++k) {
            float w0 = Ws[nt * 4 + 0][k], w1 = Ws[nt * 4 + 1][k];
            float w2 = Ws[nt * 4 + 2][k], w3 = Ws[nt * 4 + 3][k];
            float h0 = Hs[bt * 2 + 0][k], h1 = Hs[bt * 2 + 1][k];
            acc[0][0] += h0 * w0; acc[0][1] += h0 * w1;
            acc[0][2] += h0 * w2; acc[0][3] += h0 * w3;
            acc[1][0] += h1 * w0; acc[1][1] += h1 * w1;
            acc[1][2] += h1 * w2; acc[1][3] += h1 * w3;
        }
        __syncthreads();
    }
#pragma unroll
    for (int i = 0; i < 2; ++i)
#pragma unroll
        for (int j = 0; j < 4; ++j) {
            int n = n0 + nt * 4 + j;
            atomicAdd(&g_hW[(size_t)(bt * 2 + i) * CH + n], acc[i][j]);
        }
}

// ---------------- pipelined bf16-split x3 GEMM (gates) -----------------------
#define A2_STAGE (128 * 40)
#define B2_STAGE (64 * 40)
#define G2_SMEM_BYTES (3 * (A2_STAGE + B2_STAGE) * 2 * 2)

__global__ __launch_bounds__(256, 2) void gemm2_kernel(
    const __nv_bfloat16 *__restrict__ Ahi, const __nv_bfloat16 *__restrict__ Alo,
    int lda,
    const float *__restrict__ B1, int ldb1, int ksw,
    const float *__restrict__ B2, int ldb2,
    const float *__restrict__ bias1,
    float *__restrict__ C, int ldc, int K, int atomic_out) {
    extern __shared__ __align__(16) __nv_bfloat16 sm2[];
    __nv_bfloat16 *AsHi = sm2;
    __nv_bfloat16 *AsLo = AsHi + 3 * A2_STAGE;
    __nv_bfloat16 *BsHi = AsLo + 3 * A2_STAGE;
    __nv_bfloat16 *BsLo = BsHi + 3 * B2_STAGE;

    const int tid = threadIdx.x;
    const int lane = tid & 31;
    const int gid = lane >> 2;
    const int t4 = lane & 3;
    const int wm = (tid >> 5) >> 1;
    const int wn = (tid >> 5) & 1;
    const int n0 = blockIdx.x * 64;
    const int kbase = blockIdx.y * K;

    const int a_mrow = (lane & 15);
    const int a_koff = (lane >> 4) << 3;
    const int b_nrow = (lane & 7) + ((lane >> 4) << 3);
    const int b_koff = ((lane >> 3) & 1) << 3;

    const int nk = K >> 5;

    float acc[2][4][4];
#pragma unroll
    for (int i = 0; i < 2; i++)
#pragma unroll
        for (int j = 0; j < 4; j++)
#pragma unroll
            for (int c = 0; c < 4; c++) acc[i][j][c] = 0.f;

    float4 breg[2];
    auto ldB = [&](int k0) {
#pragma unroll
        for (int i = 0; i < 2; ++i) {
            int idx = tid + i * 256;
            int row = n0 + (idx >> 3);
            int k = kbase + k0 + ((idx & 7) << 2);
            const float *src = (k < ksw) ? (B1 + (size_t)row * ldb1 + k)
                                         : (B2 + (size_t)row * ldb2 + (k - ksw));
            breg[i] = *(const float4 *)src;
        }
    };
    auto stB = [&](int st) {
#pragma unroll
        for (int i = 0; i < 2; ++i) {
            int idx = tid + i * 256;
            int row = idx >> 3;
            int col = (idx & 7) << 2;
            __nv_bfloat16 h0, h1, h2, h3, l0, l1, l2, l3;
            splitf(breg[i].x, h0, l0); splitf(breg[i].y, h1, l1);
            splitf(breg[i].z, h2, l2); splitf(breg[i].w, h3, l3);
            __nv_bfloat16 *dh = BsHi + st * B2_STAGE + row * 40 + col;
            __nv_bfloat16 *dl = BsLo + st * B2_STAGE + row * 40 + col;
            *(__nv_bfloat162 *)dh       = __halves2bfloat162(h0, h1);
            *(__nv_bfloat162 *)(dh + 2) = __halves2bfloat162(h2, h3);
            *(__nv_bfloat162 *)dl       = __halves2bfloat162(l0, l1);
            *(__nv_bfloat162 *)(dl + 2) = __halves2bfloat162(l2, l3);
        }
    };
    auto cpA = [&](int st, int k0) {
#pragma unroll
        for (int i = 0; i < 2; ++i) {
            int idx = tid + i * 256;
            int row = idx >> 2;
            int col = (idx & 3) << 3;
            uint32_t dof = st * A2_STAGE + row * 40 + col;
            size_t go = (size_t)row * lda + kbase + k0 + col;
            CPASYNC16(s2u(AsHi + dof), Ahi + go);
            CPASYNC16(s2u(AsLo + dof), Alo + go);
        }
        CPCOMMIT;
    };

    cpA(0, 0);
    if (nk > 1) cpA(1, 32);
    ldB(0);
    stB(0);
    if (nk > 1) ldB(32);

    for (int kt = 0; kt < nk; ++kt) {
        if (kt < nk - 1) { CPWAIT1; } else { CPWAIT0; }
        __syncthreads();
        if (kt + 1 < nk) stB((kt + 1) % 3);
        if (kt + 2 < nk) {
            ldB((kt + 2) * 32);
            cpA((kt + 2) % 3, (kt + 2) * 32);
        }
        const int st = kt % 3;
        const __nv_bfloat16 *cAH = AsHi + st * A2_STAGE;
        const __nv_bfloat16 *cAL = AsLo + st * A2_STAGE;
        const __nv_bfloat16 *cBH = BsHi + st * B2_STAGE;
        const __nv_bfloat16 *cBL = BsLo + st * B2_STAGE;
#pragma unroll
        for (int kk = 0; kk < 32; kk += 16) {
            uint32_t ah[2][4], al[2][4];
#pragma unroll
            for (int fm = 0; fm < 2; ++fm) {
                int rowb = wm * 32 + fm * 16 + a_mrow;
                ldsm4(ah[fm][0], ah[fm][1], ah[fm][2], ah[fm][3],
                      s2u(cAH + rowb * 40 + kk + a_koff));
                ldsm4(al[fm][0], al[fm][1], al[fm][2], al[fm][3],
                      s2u(cAL + rowb * 40 + kk + a_koff));
            }
#pragma unroll
            for (int fnp = 0; fnp < 2; ++fnp) {
                uint32_t bh[4], bl[4];
                int nrow = wn * 32 + fnp * 16 + b_nrow;
                ldsm4(bh[0], bh[1], bh[2], bh[3],
                      s2u(cBH + nrow * 40 + kk + b_koff));
                ldsm4(bl[0], bl[1], bl[2], bl[3],
                      s2u(cBL + nrow * 40 + kk + b_koff));
#pragma unroll
                for (int fm = 0; fm < 2; ++fm) {
                    float *d0 = acc[fm][fnp * 2];
                    float *d1 = acc[fm][fnp * 2 + 1];
                    MMA16816(d0, ah[fm][0], ah[fm][1], ah[fm][2], ah[fm][3], bh[0], bh[1]);
                    MMA16816(d0, ah[fm][0], ah[fm][1], ah[fm][2], ah[fm][3], bl[0], bl[1]);
                    MMA16816(d0, al[fm][0], al[fm][1], al[fm][2], al[fm][3], bh[0], bh[1]);
                    MMA16816(d1, ah[fm][0], ah[fm][1], ah[fm][2], ah[fm][3], bh[2], bh[3]);
                    MMA16816(d1, ah[fm][0], ah[fm][1], ah[fm][2], ah[fm][3], bl[2], bl[3]);
                    MMA16816(d1, al[fm][0], al[fm][1], al[fm][2], al[fm][3], bh[2], bh[3]);
                }
            }
        }
    }
#pragma unroll
    for (int fm = 0; fm < 2; ++fm)
#pragma unroll
        for (int fn = 0; fn < 4; ++fn) {
            int row = wm * 32 + fm * 16 + gid;
            int col = n0 + wn * 32 + fn * 8 + (t4 << 1);
            if (atomic_out) {
                atomicAdd(&C[(size_t)row * ldc + col], acc[fm][fn][0]);
                atomicAdd(&C[(size_t)row * ldc + col + 1], acc[fm][fn][1]);
                atomicAdd(&C[(size_t)(row + 8) * ldc + col], acc[fm][fn][2]);
                atomicAdd(&C[(size_t)(row + 8) * ldc + col + 1], acc[fm][fn][3]);
            } else {
                float b0 = bias1 ? bias1[col] : 0.f;
                float b1 = bias1 ? bias1[col + 1] : 0.f;
                C[(size_t)row * ldc + col]           = acc[fm][fn][0] + b0;
                C[(size_t)row * ldc + col + 1]       = acc[fm][fn][1] + b1;
                C[(size_t)(row + 8) * ldc + col]     = acc[fm][fn][2] + b0;
                C[(size_t)(row + 8) * ldc + col + 1] = acc[fm][fn][3] + b1;
            }
        }
}

// ---------------- FC GEMM: logits = out2 @ fc_W^T + fc_b ---------------------
#define FC_STAGE_B 32768
#define FC_SMEM_BYTES (3 * FC_STAGE_B)

__global__ __launch_bounds__(256, 2) void fc_kernel(
    const __nv_bfloat16 *__restrict__ Ahi, const __nv_bfloat16 *__restrict__ Alo,
    const float *__restrict__ B, const float *__restrict__ bias,
    float *__restrict__ C) {
    extern __shared__ __align__(16) char smem[];
    const uint32_t sb = s2u(smem);

    const int tid = threadIdx.x;
    const int lane = tid & 31;
    const int gid = lane >> 2;
    const int t4 = lane & 3;
    const int wm = (tid >> 5) >> 1;
    const int wn = (tid >> 5) & 1;
    const int n0 = blockIdx.x * 128;

    const int a_mrow = (lane & 15);
    const int a_ch = lane >> 4;
    const int b_nrow = (lane & 7) + ((lane >> 4) << 3);
    const int b_ch = (lane >> 3) & 1;

    float acc[2][8][4];
#pragma unroll
    for (int i = 0; i < 2; i++)
#pragma unroll
        for (int j = 0; j < 8; j++)
#pragma unroll
            for (int c = 0; c < 4; c++) acc[i][j][c] = 0.f;

    float4 breg[4];
    auto ldB = [&](int k0) {
#pragma unroll
        for (int i = 0; i < 4; ++i) {
            int idx = tid + i * 256;
            int row = n0 + (idx >> 3);
            int col = (idx & 7) << 2;
            breg[i] = *(const float4 *)(B + (size_t)row * 2048 + k0 + col);
        }
    };
    auto stB = [&](int st) {
#pragma unroll
        for (int i = 0; i < 4; ++i) {
            int idx = tid + i * 256;
            int row = idx >> 3;
            int colf = (idx & 7) << 2;
            int boff = colf * 2;
            int ch = boff >> 4;
            int inner = boff & 15;
            uint32_t off = (uint32_t)st * FC_STAGE_B + 16384 + row * 64 +
                           ((uint32_t)(ch ^ ((row >> 1) & 3)) << 4) + inner;
            __nv_bfloat16 h0, h1, h2, h3, l0, l1, l2, l3;
            splitf(breg[i].x, h0, l0); splitf(breg[i].y, h1, l1);
            splitf(breg[i].z, h2, l2); splitf(breg[i].w, h3, l3);
            *(__nv_bfloat162 *)(smem + off)        = __halves2bfloat162(h0, h1);
            *(__nv_bfloat162 *)(smem + off + 4)    = __halves2bfloat162(h2, h3);
            *(__nv_bfloat162 *)(smem + off + 8192) = __halves2bfloat162(l0, l1);
            *(__nv_bfloat162 *)(smem + off + 8196) = __halves2bfloat162(l2, l3);
        }
    };
    auto cpA = [&](int st, int k0) {
#pragma unroll
        for (int i = 0; i < 2; ++i) {
            int idx = tid + i * 256;
            int row = idx >> 2;
            int ch = idx & 3;
            uint32_t so = (uint32_t)st * FC_STAGE_B + row * 64 +
                          ((uint32_t)(ch ^ ((row >> 1) & 3)) << 4);
            size_t go = (size_t)row * 2048 + k0 + ch * 8;
            CPASYNC16(sb + so, Ahi + go);
            CPASYNC16(sb + 8192 + so, Alo + go);
        }
        CPCOMMIT;
    };

    cpA(0, 0);
    cpA(1, 32);
    ldB(0);
    stB(0);
    ldB(32);

    const int nk = 2048 / 32;
    for (int kt = 0; kt < nk; ++kt) {
        if (kt < nk - 1) { CPWAIT1; } else { CPWAIT0; }
        __syncthreads();
        if (kt + 1 < nk) stB((kt + 1) % 3);
        if (kt + 2 < nk) {
            ldB((kt + 2) * 32);
            cpA((kt + 2) % 3, (kt + 2) * 32);
        }
        const uint32_t csb = sb + (uint32_t)(kt % 3) * FC_STAGE_B;
#pragma unroll
        for (int kk = 0; kk < 32; kk += 16) {
            uint32_t ah[2][4], al[2][4];
#pragma unroll
            for (int fm = 0; fm < 2; ++fm) {
                int rowb = wm * 32 + fm * 16 + a_mrow;
                uint32_t sw = (uint32_t)(((kk >> 3) + a_ch) ^ ((rowb >> 1) & 3));
                uint32_t ad = csb + rowb * 64 + (sw << 4);
                ldsm4(ah[fm][0], ah[fm][1], ah[fm][2], ah[fm][3], ad);
                ldsm4(al[fm][0], al[fm][1], al[fm][2], al[fm][3], ad + 8192);
            }
#pragma unroll
            for (int fnp = 0; fnp < 4; ++fnp) {
                uint32_t bh[4], bl[4];
                int nrow = wn * 64 + fnp * 16 + b_nrow;
                uint32_t sw = (uint32_t)(((kk >> 3) + b_ch) ^ ((nrow >> 1) & 3));
                uint32_t bd = csb + 16384 + nrow * 64 + (sw << 4);
                ldsm4(bh[0], bh[1], bh[2], bh[3], bd);
                ldsm4(bl[0], bl[1], bl[2], bl[3], bd + 8192);
#pragma unroll
                for (int fm = 0; fm < 2; ++fm) {
                    float *d0 = acc[fm][fnp * 2];
                    float *d1 = acc[fm][fnp * 2 + 1];
                    MMA16816(d0, ah[fm][0], ah[fm][1], ah[fm][2], ah[fm][3], bh[0], bh[1]);
                    MMA16816(d0, ah[fm][0], ah[fm][1], ah[fm][2], ah[fm][3], bl[0], bl[1]);
                    MMA16816(d0, al[fm][0], al[fm][1], al[fm][2], al[fm][3], bh[0], bh[1]);
                    MMA16816(d1, ah[fm][0], ah[fm][1], ah[fm][2], ah[fm][3], bh[2], bh[3]);
                    MMA16816(d1, ah[fm][0], ah[fm][1], ah[fm][2], ah[fm][3], bl[2], bl[3]);
                    MMA16816(d1, al[fm][0], al[fm][1], al[fm][2], al[fm][3], bh[2], bh[3]);
                }
            }
        }
    }
#pragma unroll
    for (int fm = 0; fm < 2; ++fm)
#pragma unroll
        for (int fn = 0; fn < 8; ++fn) {
            int row = wm * 32 + fm * 16 + gid;
            int col = n0 + wn * 64 + fn * 8 + (t4 << 1);
            float b0 = bias[col], b1 = bias[col + 1];
            C[(size_t)row * CV + col]           = acc[fm][fn][0] + b0;
            C[(size_t)row * CV + col + 1]       = acc[fm][fn][1] + b1;
            C[(size_t)(row + 8) * CV + col]     = acc[fm][fn][2] + b0;
            C[(size_t)(row + 8) * CV + col + 1] = acc[fm][fn][3] + b1;
        }
}

// ---------------- fused energy GEMM + tanh + v-dot -> score[B,S] -------------
// R10 config (proven 236us / tensor 71.5%): tile 128x128x32, grid (8, 128),
// 256 threads, 2 CTA/SM, 3-stage cp.async, ONE barrier per k-tile,
// swizzled 64B rows. Writes RAW scores (softmax deferred to context kernel).
#define AS_STAGE_B 32768
#define ATTN_SMEM_BYTES (3 * AS_STAGE_B + 512)

__global__ __launch_bounds__(256, 2) void attn_score_kernel(const float *__restrict__ v) {
    extern __shared__ __align__(16) char smem[];
    const uint32_t sb = s2u(smem);
    float *red = (float *)(smem + 3 * AS_STAGE_B);

    const int b = blockIdx.y;
    const int n0 = blockIdx.x * 128;
    const int tid = threadIdx.x;
    const int lane = tid & 31;
    const int gid = lane >> 2;
    const int t4 = lane & 3;
    const int wm = (tid >> 5) >> 1;
    const int wn = (tid >> 5) & 1;
    if (tid < 128) red[tid] = 0.f;

    const int a_mrow = (lane & 15);
    const int a_ch = lane >> 4;
    const int b_nrow = (lane & 7) + ((lane >> 4) << 3);
    const int b_ch = (lane >> 3) & 1;

    const int ld_row = tid >> 2;
    const int ld_ch = tid & 3;

    float acc[2][8][4];
#pragma unroll
    for (int i = 0; i < 2; i++)
#pragma unroll
        for (int j = 0; j < 8; j++)
#pragma unroll
            for (int c = 0; c < 4; c++) acc[i][j][c] = 0.f;

#define LOAD_STAGE(st, k0)                                                     \
    do {                                                                       \
        _Pragma("unroll") for (int i = 0; i < 2; ++i) {                        \
            int row = ld_row + i * 64;                                         \
            uint32_t so = (uint32_t)(st) * AS_STAGE_B + row * 64 +             \
                          ((uint32_t)(ld_ch ^ ((row >> 1) & 3)) << 4);         \
            size_t goA = (size_t)(b * 128 + row) * CH + (k0) + ld_ch * 8;      \
            size_t goB = (size_t)(n0 + row) * CH + (k0) + ld_ch * 8;           \
            CPASYNC16(sb + so, g_enc_hi + goA);                                \
            CPASYNC16(sb + 8192 + so, g_enc_lo + goA);                         \
            CPASYNC16(sb + 16384 + so, g_w2_hi + goB);                         \
            CPASYNC16(sb + 24576 + so, g_w2_lo + goB);                         \
        }                                                                      \
        CPCOMMIT;                                                              \
    } while (0)

    LOAD_STAGE(0, 0);
    LOAD_STAGE(1, 32);
    for (int kt = 0; kt < 32; ++kt) {
        if (kt < 31) { CPWAIT1; } else { CPWAIT0; }
        __syncthreads();
        if (kt + 2 < 32) LOAD_STAGE((kt + 2) % 3, (kt + 2) * 32);
        const uint32_t csb = sb + (uint32_t)(kt % 3) * AS_STAGE_B;
#pragma unroll
        for (int kk = 0; kk < 32; kk += 16) {
            uint32_t ah[2][4], al[2][4];
#pragma unroll
            for (int fm = 0; fm < 2; ++fm) {
                int rowb = wm * 32 + fm * 16 + a_mrow;
                uint32_t sw = (uint32_t)(((kk >> 3) + a_ch) ^ ((rowb >> 1) & 3));
                uint32_t ad = csb + rowb * 64 + (sw << 4);
                ldsm4(ah[fm][0], ah[fm][1], ah[fm][2], ah[fm][3], ad);
                ldsm4(al[fm][0], al[fm][1], al[fm][2], al[fm][3], ad + 8192);
            }
#pragma unroll
            for (int fnp = 0; fnp < 4; ++fnp) {
                uint32_t bh[4], bl[4];
                int nrow = wn * 64 + fnp * 16 + b_nrow;
                uint32_t sw = (uint32_t)(((kk >> 3) + b_ch) ^ ((nrow >> 1) & 3));
                uint32_t bd = csb + 16384 + nrow * 64 + (sw << 4);
                ldsm4(bh[0], bh[1], bh[2], bh[3], bd);
                ldsm4(bl[0], bl[1], bl[2], bl[3], bd + 8192);
#pragma unroll
                for (int fm = 0; fm < 2; ++fm) {
                    float *d0 = acc[fm][fnp * 2];
                    float *d1 = acc[fm][fnp * 2 + 1];
                    MMA16816(d0, ah[fm][0], ah[fm][1], ah[fm][2], ah[fm][3], bh[0], bh[1]);
                    MMA16816(d0, ah[fm][0], ah[fm][1], ah[fm][2], ah[fm][3], bl[0], bl[1]);
                    MMA16816(d0, al[fm][0], al[fm][1], al[fm][2], al[fm][3], bh[0], bh[1]);
                    MMA16816(d1, ah[fm][0], ah[fm][1], ah[fm][2], ah[fm][3], bh[2], bh[3]);
                    MMA16816(d1, ah[fm][0], ah[fm][1], ah[fm][2], ah[fm][3], bl[2], bl[3]);
                    MMA16816(d1, al[fm][0], al[fm][1], al[fm][2], al[fm][3], bh[2], bh[3]);
                }
            }
        }
    }
    __syncthreads();

    const float *hWb = g_hW + (size_t)b * CH;
    float pA[2] = {0.f, 0.f}, pB[2] = {0.f, 0.f};
#pragma unroll
    for (int fm = 0; fm < 2; ++fm)
#pragma unroll
        for (int fn = 0; fn < 8; ++fn) {
            int col = n0 + wn * 64 + fn * 8 + (t4 << 1);
            float hw0 = hWb[col], hw1 = hWb[col + 1];
            float v0 = v[col], v1 = v[col + 1];
            pA[fm] += tanhf(acc[fm][fn][0] + hw0) * v0 +
                      tanhf(acc[fm][fn][1] + hw1) * v1;
            pB[fm] += tanhf(acc[fm][fn][2] + hw0) * v0 +
                      tanhf(acc[fm][fn][3] + hw1) * v1;
        }
#pragma unroll
    for (int fm = 0; fm < 2; ++fm)
#pragma unroll
        for (int j = 0; j < 2; ++j) {
            float val = j ? pB[fm] : pA[fm];
            val += __shfl_xor_sync(0xffffffffu, val, 1);
            val += __shfl_xor_sync(0xffffffffu, val, 2);
            if (t4 == 0) atomicAdd(&red[wm * 32 + fm * 16 + j * 8 + gid], val);
        }
    __syncthreads();
    if (tid < 128) atomicAdd(&g_score[b * 128 + tid], red[tid]);
}

// ---------------- context (+inline softmax) + assemble xin -------------------
// grid (128, 4): b x H-quadrant. Each CTA computes softmax of g_score[b,:]
// locally (raw scores preserved); q==0 writes attn_weights output.
__global__ __launch_bounds__(256) void context_kernel(
    const int *__restrict__ x, const float *__restrict__ emb_table,
    const float *__restrict__ hidden, const float *__restrict__ enc,
    float *__restrict__ out_attn) {
    const int b = blockIdx.x;
    const int q = blockIdx.y;
    const int t = threadIdx.x;
    __shared__ float w_s[128];
    __shared__ float r_s[128];
    // inline softmax over 128 raw scores
    if (t < 128) {
        float s = g_score[b * 128 + t];
        w_s[t] = s;
        r_s[t] = s;
    }
    __syncthreads();
#pragma unroll
    for (int st = 64; st > 0; st >>= 1) {
        if (t < st) r_s[t] = fmaxf(r_s[t], r_s[t + st]);
        __syncthreads();
    }
    float mx = r_s[0];
    __syncthreads();
    if (t < 128) r_s[t] = expf(w_s[t] - mx);
    __syncthreads();
    float e_t = (t < 128) ? r_s[t] : 0.f;
#pragma unroll
    for (int st = 64; st > 0; st >>= 1) {
        if (t < st) r_s[t] += r_s[t + st];
        __syncthreads();
    }
    float inv = 1.0f / r_s[0];
    __syncthreads();
    if (t < 128) {
        float w = e_t * inv;
        w_s[t] = w;
        if (q == 0) out_attn[b * 128 + t] = w;
    }

    const int h = q * 256 + t;
    if (q < 2) {
        int i = q * 256 + t;
        __nv_bfloat16 hi, lo;
        splitf(emb_table[(size_t)x[b] * CE + i], hi, lo);
        g_xin_hi[(size_t)b * 2560 + i] = hi;
        g_xin_lo[(size_t)b * 2560 + i] = lo;
    }
    {
        __nv_bfloat16 hi, lo;
        splitf(hidden[(size_t)b * CH + h], hi, lo);
        g_xin_hi[(size_t)b * 2560 + 1536 + h] = hi;
        g_xin_lo[(size_t)b * 2560 + 1536 + h] = lo;
    }
    __syncthreads();
    float acc = 0.f;
    const float *encb = enc + (size_t)b * CS * CH + h;
#pragma unroll 8
    for (int s = 0; s < CS; ++s) acc += w_s[s] * encb[(size_t)s * CH];
    __nv_bfloat16 hi, lo;
    splitf(acc, hi, lo);
    g_xin_hi[(size_t)b * 2560 + 512 + h] = hi;
    g_xin_lo[(size_t)b * 2560 + 512 + h] = lo;
    g_out2_hi[(size_t)b * 2048 + 1024 + h] = hi;
    g_out2_lo[(size_t)b * 2048 + 1024 + h] = lo;
}

// ---------------- LSTM pointwise ---------------------------------------------
__global__ __launch_bounds__(256) void lstm_kernel(
    const float *__restrict__ cell, float *__restrict__ out_h,
    float *__restrict__ out_c) {
    int id = blockIdx.x * 256 + threadIdx.x;
    int b = id >> 10;
    int h = id & 1023;
    const float *gt = g_gates + (size_t)b * 4096;
    float gi = gt[h], gf = gt[1024 + h], gg = gt[2048 + h], go = gt[3072 + h];
    float c_old = cell[(size_t)b * CH + h];
    float cn = sigf(gf) * c_old + sigf(gi) * tanhf(gg);
    float hn = sigf(go) * tanhf(cn);
    out_h[(size_t)b * CH + h] = hn;
    out_c[(size_t)b * CH + h] = cn;
    __nv_bfloat16 hi, lo;
    splitf(hn, hi, lo);
    g_out2_hi[(size_t)b * 2048 + h] = hi;
    g_out2_lo[(size_t)b * 2048 + h] = lo;
}

// ---------------- launch ------------------------------------------------------
extern "C" void kernel_launch(void *const *d_in, const int *in_sizes, int n_in,
                              void *d_out, int out_size) {
    (void)in_sizes; (void)n_in; (void)out_size;
    const int *x           = (const int *)d_in[0];
    const float *hidden    = (const float *)d_in[1];
    const float *cell      = (const float *)d_in[2];
    const float *enc       = (const float *)d_in[3];
    const float *emb_table = (const float *)d_in[4];
    const float *attn_W    = (const float *)d_in[5];
    const float *attn_b    = (const float *)d_in[6];
    const float *v         = (const float *)d_in[7];
    const float *W_ih      = (const float *)d_in[8];
    const float *W_hh      = (const float *)d_in[9];
    const float *b_ih      = (const float *)d_in[10];
    const float *b_hh      = (const float *)d_in[11];
    const float *fc_W      = (const float *)d_in[12];
    const float *fc_b      = (const float *)d_in[13];

    float *out        = (float *)d_out;
    float *out_logits = out;
    float *out_h      = out + (size_t)CB * CV;
    float *out_c      = out_h + (size_t)CB * CH;
    float *out_attn   = out_c + (size_t)CB * CH;

    float *gatesp = nullptr;
    __nv_bfloat16 *o2h = nullptr, *o2l = nullptr, *xih = nullptr, *xil = nullptr;
    cudaGetSymbolAddress((void **)&gatesp, g_gates);
    cudaGetSymbolAddress((void **)&o2h, g_out2_hi);
    cudaGetSymbolAddress((void **)&o2l, g_out2_lo);
    cudaGetSymbolAddress((void **)&xih, g_xin_hi);
    cudaGetSymbolAddress((void **)&xil, g_xin_lo);

    cudaFuncSetAttribute(attn_score_kernel,
                         cudaFuncAttributeMaxDynamicSharedMemorySize,
                         ATTN_SMEM_BYTES);
    cudaFuncSetAttribute(gemm2_kernel,
                         cudaFuncAttributeMaxDynamicSharedMemorySize,
                         G2_SMEM_BYTES);
    cudaFuncSetAttribute(fc_kernel,
                         cudaFuncAttributeMaxDynamicSharedMemorySize,
                         FC_SMEM_BYTES);

    // 1) merged: split enc + split attn_W[:,H:2H] + zero score + seed biases
    conv_all_kernel<<<16384, 256>>>(enc, attn_W, attn_b, b_ih, b_hh);
    // 2) hW += h_last @ attn_W[:, :H]^T  (K-split x4, atomic)
    hw_kernel<<<dim3(64, 4), 256>>>(hidden, attn_W);
    // 3) spacer-free: fused energy GEMM + tanh + v-dot -> raw g_score
    attn_score_kernel<<<dim3(8, CB), 256, ATTN_SMEM_BYTES>>>(v);
    // 4) context (+inline softmax) + xin assembly + attn_weights output
    context_kernel<<<dim3(CB, 4), 256>>>(x, emb_table, hidden, enc, out_attn);
    // 5) gates += xin @ [W_ih|W_hh]^T  (single launch, K-split via grid.y)
    gemm2_kernel<<<dim3(4096 / 64, 4), 256, G2_SMEM_BYTES>>>(
        xih, xil, 2560,
        W_ih, 1536, 1536, W_hh, CH,
        nullptr, gatesp, 4096, 640, 1);
    // 6) LSTM pointwise
    lstm_kernel<<<(CB * CH) / 256, 256>>>(cell, out_h, out_c);
    // 7) logits = [h_new|context] @ fc_W^T + fc_b
    fc_kernel<<<CV / 128, 256, FC_SMEM_BYTES>>>(o2h, o2l, fc_W, fc_b, out_logits);
}

// round 13
// speedup vs baseline: 1.0951x; 1.0404x over previous
#include <cuda_runtime.h>
#include <cuda_bf16.h>
#include <stdint.h>
#include <math.h>

#define CB 128
#define CS 128
#define CH 1024
#define CE 512
#define CV 32000

// ---------------- scratch (__device__ globals; no allocations allowed) -------
__device__ __align__(16) float g_hW[CB * CH];
__device__ __align__(16) float g_score[CB * CS];   // raw scores (softmax done in context)
__device__ __align__(16) float g_gates[CB * 4096];
__device__ __align__(16) __nv_bfloat16 g_xin_hi[CB * 2560];   // [emb|context|h_last]
__device__ __align__(16) __nv_bfloat16 g_xin_lo[CB * 2560];
__device__ __align__(16) __nv_bfloat16 g_out2_hi[CB * 2048];  // [h_new | context]
__device__ __align__(16) __nv_bfloat16 g_out2_lo[CB * 2048];
__device__ __align__(16) __nv_bfloat16 g_enc_hi[CB * CS * CH];
__device__ __align__(16) __nv_bfloat16 g_enc_lo[CB * CS * CH];
__device__ __align__(16) __nv_bfloat16 g_w2_hi[CH * CH];      // attn_W[:, H:2H] as [n][k]
__device__ __align__(16) __nv_bfloat16 g_w2_lo[CH * CH];

// ---------------- helpers ----------------------------------------------------
__device__ __forceinline__ void splitf(float x, __nv_bfloat16 &hi, __nv_bfloat16 &lo) {
    hi = __float2bfloat16_rn(x);
    lo = __float2bfloat16_rn(x - __bfloat162float(hi));
}
__device__ __forceinline__ float sigf(float x) { return 1.0f / (1.0f + expf(-x)); }
__device__ __forceinline__ uint32_t s2u(const void *p) {
    return (uint32_t)__cvta_generic_to_shared(p);
}
__device__ __forceinline__ void ldsm4(uint32_t &r0, uint32_t &r1, uint32_t &r2,
                                      uint32_t &r3, uint32_t addr) {
    asm volatile("ldmatrix.sync.aligned.m8n8.x4.shared.b16 {%0,%1,%2,%3}, [%4];"
                 : "=r"(r0), "=r"(r1), "=r"(r2), "=r"(r3)
                 : "r"(addr));
}

#define MMA16816(d, a0, a1, a2, a3, b0, b1)                                    \
    asm volatile(                                                              \
        "mma.sync.aligned.m16n8k16.row.col.f32.bf16.bf16.f32 "                 \
        "{%0,%1,%2,%3},{%4,%5,%6,%7},{%8,%9},{%0,%1,%2,%3};\n"                 \
        : "+f"(d[0]), "+f"(d[1]), "+f"(d[2]), "+f"(d[3])                       \
        : "r"(a0), "r"(a1), "r"(a2), "r"(a3), "r"(b0), "r"(b1))

#define CPASYNC16(dst, src)                                                    \
    asm volatile("cp.async.cg.shared.global [%0], [%1], 16;\n" ::"r"(dst),     \
                 "l"(src))
#define CPCOMMIT asm volatile("cp.async.commit_group;\n" ::)
#define CPWAIT1 asm volatile("cp.async.wait_group 1;\n" ::)
#define CPWAIT0 asm volatile("cp.async.wait_group 0;\n" ::)

// ---------------- merged precision split + init ------------------------------
__global__ __launch_bounds__(256) void conv_all_kernel(
    const float *__restrict__ enc, const float *__restrict__ attn_W,
    const float *__restrict__ attn_b, const float *__restrict__ b_ih,
    const float *__restrict__ b_hh) {
    size_t idx = (size_t)blockIdx.x * 256 + threadIdx.x;  // float4 index over enc
    float4 v4 = ((const float4 *)enc)[idx];
    __nv_bfloat16 h0, h1, h2, h3, l0, l1, l2, l3;
    splitf(v4.x, h0, l0); splitf(v4.y, h1, l1);
    splitf(v4.z, h2, l2); splitf(v4.w, h3, l3);
    ((__nv_bfloat162 *)g_enc_hi)[idx * 2 + 0] = __halves2bfloat162(h0, h1);
    ((__nv_bfloat162 *)g_enc_hi)[idx * 2 + 1] = __halves2bfloat162(h2, h3);
    ((__nv_bfloat162 *)g_enc_lo)[idx * 2 + 0] = __halves2bfloat162(l0, l1);
    ((__nv_bfloat162 *)g_enc_lo)[idx * 2 + 1] = __halves2bfloat162(l2, l3);

    if (blockIdx.x >= 1024) return;
    size_t idx2 = (size_t)blockIdx.x * 256 + threadIdx.x;  // 262144 float4s of w2
    if (blockIdx.x < 64) g_score[blockIdx.x * 256 + threadIdx.x] = 0.f;
    if (blockIdx.x < 512) {
        int i = blockIdx.x * 256 + threadIdx.x;
        g_hW[i] = attn_b[i & (CH - 1)];
    }
    {
        int i2 = ((int)blockIdx.x * 256 + (int)threadIdx.x) * 2;
        g_gates[i2]     = b_ih[i2 & 4095] + b_hh[i2 & 4095];
        g_gates[i2 + 1] = b_ih[(i2 + 1) & 4095] + b_hh[(i2 + 1) & 4095];
    }
    int n = (int)(idx2 >> 8);
    int k = (int)(idx2 & 255) << 2;
    float4 w4 = *(const float4 *)(attn_W + (size_t)n * 2048 + 1024 + k);
    splitf(w4.x, h0, l0); splitf(w4.y, h1, l1);
    splitf(w4.z, h2, l2); splitf(w4.w, h3, l3);
    size_t o = ((size_t)n * CH + k) >> 1;
    ((__nv_bfloat162 *)g_w2_hi)[o + 0] = __halves2bfloat162(h0, h1);
    ((__nv_bfloat162 *)g_w2_hi)[o + 1] = __halves2bfloat162(h2, h3);
    ((__nv_bfloat162 *)g_w2_lo)[o + 0] = __halves2bfloat162(l0, l1);
    ((__nv_bfloat162 *)g_w2_lo)[o + 1] = __halves2bfloat162(l2, l3);
}

// ---------------- small GEMM: hW += hidden @ W1^T (K-split, atomic) ----------
__global__ __launch_bounds__(256) void hw_kernel(const float *__restrict__ hidden,
                                                 const float *__restrict__ attn_W) {
    __shared__ float Hs[128][65];
    __shared__ float Ws[16][65];
    const int tid = threadIdx.x;
    const int n0 = blockIdx.x * 16;
    const int kbase = blockIdx.y * 256;
    const int bt = tid & 63;
    const int nt = tid >> 6;
    float acc[2][4] = {{0.f, 0.f, 0.f, 0.f}, {0.f, 0.f, 0.f, 0.f}};

    for (int kc = 0; kc < 4; ++kc) {
        const int k0 = kbase + kc * 64;
#pragma unroll
        for (int i = 0; i < 8; ++i) {
            int idx = tid + 256 * i;
            int row = idx >> 4;
            int cv = (idx & 15) << 2;
            float4 v4 = *(const float4 *)(hidden + (size_t)row * CH + k0 + cv);
            Hs[row][cv] = v4.x; Hs[row][cv + 1] = v4.y;
            Hs[row][cv + 2] = v4.z; Hs[row][cv + 3] = v4.w;
        }
        {
            int row = tid >> 4;
            int cv = (tid & 15) << 2;
            float4 v4 = *(const float4 *)(attn_W + (size_t)(n0 + row) * 2048 + k0 + cv);
            Ws[row][cv] = v4.x; Ws[row][cv + 1] = v4.y;
            Ws[row][cv + 2] = v4.z; Ws[row][cv + 3] = v4.w;
        }
        __syncthreads();
#pragma unroll 8
        for (int k = 0; k < 64; ++k) {
            float w0 = Ws[nt * 4 + 0][k], w1 = Ws[nt * 4 + 1][k];
            float w2 = Ws[nt * 4 + 2][k], w3 = Ws[nt * 4 + 3][k];
            float h0 = Hs[bt * 2 + 0][k], h1 = Hs[bt * 2 + 1][k];
            acc[0][0] += h0 * w0; acc[0][1] += h0 * w1;
            acc[0][2] += h0 * w2; acc[0][3] += h0 * w3;
            acc[1][0] += h1 * w0; acc[1][1] += h1 * w1;
            acc[1][2] += h1 * w2; acc[1][3] += h1 * w3;
        }
        __syncthreads();
    }
#pragma unroll
    for (int i = 0; i < 2; ++i)
#pragma unroll
        for (int j = 0; j < 4; ++j) {
            int n = n0 + nt * 4 + j;
            atomicAdd(&g_hW[(size_t)(bt * 2 + i) * CH + n], acc[i][j]);
        }
}

// ---------------- pipelined bf16-split x3 GEMM (gates) -----------------------
#define A2_STAGE (128 * 40)
#define B2_STAGE (64 * 40)
#define G2_SMEM_BYTES (3 * (A2_STAGE + B2_STAGE) * 2 * 2)

__global__ __launch_bounds__(256, 2) void gemm2_kernel(
    const __nv_bfloat16 *__restrict__ Ahi, const __nv_bfloat16 *__restrict__ Alo,
    int lda,
    const float *__restrict__ B1, int ldb1, int ksw,
    const float *__restrict__ B2, int ldb2,
    const float *__restrict__ bias1,
    float *__restrict__ C, int ldc, int K, int atomic_out) {
    extern __shared__ __align__(16) __nv_bfloat16 sm2[];
    __nv_bfloat16 *AsHi = sm2;
    __nv_bfloat16 *AsLo = AsHi + 3 * A2_STAGE;
    __nv_bfloat16 *BsHi = AsLo + 3 * A2_STAGE;
    __nv_bfloat16 *BsLo = BsHi + 3 * B2_STAGE;

    const int tid = threadIdx.x;
    const int lane = tid & 31;
    const int gid = lane >> 2;
    const int t4 = lane & 3;
    const int wm = (tid >> 5) >> 1;
    const int wn = (tid >> 5) & 1;
    const int n0 = blockIdx.x * 64;
    const int kbase = blockIdx.y * K;

    const int a_mrow = (lane & 15);
    const int a_koff = (lane >> 4) << 3;
    const int b_nrow = (lane & 7) + ((lane >> 4) << 3);
    const int b_koff = ((lane >> 3) & 1) << 3;

    const int nk = K >> 5;

    float acc[2][4][4];
#pragma unroll
    for (int i = 0; i < 2; i++)
#pragma unroll
        for (int j = 0; j < 4; j++)
#pragma unroll
            for (int c = 0; c < 4; c++) acc[i][j][c] = 0.f;

    float4 breg[2];
    auto ldB = [&](int k0) {
#pragma unroll
        for (int i = 0; i < 2; ++i) {
            int idx = tid + i * 256;
            int row = n0 + (idx >> 3);
            int k = kbase + k0 + ((idx & 7) << 2);
            const float *src = (k < ksw) ? (B1 + (size_t)row * ldb1 + k)
                                         : (B2 + (size_t)row * ldb2 + (k - ksw));
            breg[i] = *(const float4 *)src;
        }
    };
    auto stB = [&](int st) {
#pragma unroll
        for (int i = 0; i < 2; ++i) {
            int idx = tid + i * 256;
            int row = idx >> 3;
            int col = (idx & 7) << 2;
            __nv_bfloat16 h0, h1, h2, h3, l0, l1, l2, l3;
            splitf(breg[i].x, h0, l0); splitf(breg[i].y, h1, l1);
            splitf(breg[i].z, h2, l2); splitf(breg[i].w, h3, l3);
            __nv_bfloat16 *dh = BsHi + st * B2_STAGE + row * 40 + col;
            __nv_bfloat16 *dl = BsLo + st * B2_STAGE + row * 40 + col;
            *(__nv_bfloat162 *)dh       = __halves2bfloat162(h0, h1);
            *(__nv_bfloat162 *)(dh + 2) = __halves2bfloat162(h2, h3);
            *(__nv_bfloat162 *)dl       = __halves2bfloat162(l0, l1);
            *(__nv_bfloat162 *)(dl + 2) = __halves2bfloat162(l2, l3);
        }
    };
    auto cpA = [&](int st, int k0) {
#pragma unroll
        for (int i = 0; i < 2; ++i) {
            int idx = tid + i * 256;
            int row = idx >> 2;
            int col = (idx & 3) << 3;
            uint32_t dof = st * A2_STAGE + row * 40 + col;
            size_t go = (size_t)row * lda + kbase + k0 + col;
            CPASYNC16(s2u(AsHi + dof), Ahi + go);
            CPASYNC16(s2u(AsLo + dof), Alo + go);
        }
        CPCOMMIT;
    };

    cpA(0, 0);
    if (nk > 1) cpA(1, 32);
    ldB(0);
    stB(0);
    if (nk > 1) ldB(32);

    for (int kt = 0; kt < nk; ++kt) {
        if (kt < nk - 1) { CPWAIT1; } else { CPWAIT0; }
        __syncthreads();
        if (kt + 1 < nk) stB((kt + 1) % 3);
        if (kt + 2 < nk) {
            ldB((kt + 2) * 32);
            cpA((kt + 2) % 3, (kt + 2) * 32);
        }
        const int st = kt % 3;
        const __nv_bfloat16 *cAH = AsHi + st * A2_STAGE;
        const __nv_bfloat16 *cAL = AsLo + st * A2_STAGE;
        const __nv_bfloat16 *cBH = BsHi + st * B2_STAGE;
        const __nv_bfloat16 *cBL = BsLo + st * B2_STAGE;
#pragma unroll
        for (int kk = 0; kk < 32; kk += 16) {
            uint32_t ah[2][4], al[2][4];
#pragma unroll
            for (int fm = 0; fm < 2; ++fm) {
                int rowb = wm * 32 + fm * 16 + a_mrow;
                ldsm4(ah[fm][0], ah[fm][1], ah[fm][2], ah[fm][3],
                      s2u(cAH + rowb * 40 + kk + a_koff));
                ldsm4(al[fm][0], al[fm][1], al[fm][2], al[fm][3],
                      s2u(cAL + rowb * 40 + kk + a_koff));
            }
#pragma unroll
            for (int fnp = 0; fnp < 2; ++fnp) {
                uint32_t bh[4], bl[4];
                int nrow = wn * 32 + fnp * 16 + b_nrow;
                ldsm4(bh[0], bh[1], bh[2], bh[3],
                      s2u(cBH + nrow * 40 + kk + b_koff));
                ldsm4(bl[0], bl[1], bl[2], bl[3],
                      s2u(cBL + nrow * 40 + kk + b_koff));
#pragma unroll
                for (int fm = 0; fm < 2; ++fm) {
                    float *d0 = acc[fm][fnp * 2];
                    float *d1 = acc[fm][fnp * 2 + 1];
                    MMA16816(d0, ah[fm][0], ah[fm][1], ah[fm][2], ah[fm][3], bh[0], bh[1]);
                    MMA16816(d0, ah[fm][0], ah[fm][1], ah[fm][2], ah[fm][3], bl[0], bl[1]);
                    MMA16816(d0, al[fm][0], al[fm][1], al[fm][2], al[fm][3], bh[0], bh[1]);
                    MMA16816(d1, ah[fm][0], ah[fm][1], ah[fm][2], ah[fm][3], bh[2], bh[3]);
                    MMA16816(d1, ah[fm][0], ah[fm][1], ah[fm][2], ah[fm][3], bl[2], bl[3]);
                    MMA16816(d1, al[fm][0], al[fm][1], al[fm][2], al[fm][3], bh[2], bh[3]);
                }
            }
        }
    }
#pragma unroll
    for (int fm = 0; fm < 2; ++fm)
#pragma unroll
        for (int fn = 0; fn < 4; ++fn) {
            int row = wm * 32 + fm * 16 + gid;
            int col = n0 + wn * 32 + fn * 8 + (t4 << 1);
            if (atomic_out) {
                atomicAdd(&C[(size_t)row * ldc + col], acc[fm][fn][0]);
                atomicAdd(&C[(size_t)row * ldc + col + 1], acc[fm][fn][1]);
                atomicAdd(&C[(size_t)(row + 8) * ldc + col], acc[fm][fn][2]);
                atomicAdd(&C[(size_t)(row + 8) * ldc + col + 1], acc[fm][fn][3]);
            } else {
                float b0 = bias1 ? bias1[col] : 0.f;
                float b1 = bias1 ? bias1[col + 1] : 0.f;
                C[(size_t)row * ldc + col]           = acc[fm][fn][0] + b0;
                C[(size_t)row * ldc + col + 1]       = acc[fm][fn][1] + b1;
                C[(size_t)(row + 8) * ldc + col]     = acc[fm][fn][2] + b0;
                C[(size_t)(row + 8) * ldc + col + 1] = acc[fm][fn][3] + b1;
            }
        }
}

// ---------------- FC GEMM: logits = out2 @ fc_W^T + fc_b ---------------------
#define FC_STAGE_B 32768
#define FC_SMEM_BYTES (3 * FC_STAGE_B)

__global__ __launch_bounds__(256, 2) void fc_kernel(
    const __nv_bfloat16 *__restrict__ Ahi, const __nv_bfloat16 *__restrict__ Alo,
    const float *__restrict__ B, const float *__restrict__ bias,
    float *__restrict__ C) {
    extern __shared__ __align__(16) char smem[];
    const uint32_t sb = s2u(smem);

    const int tid = threadIdx.x;
    const int lane = tid & 31;
    const int gid = lane >> 2;
    const int t4 = lane & 3;
    const int wm = (tid >> 5) >> 1;
    const int wn = (tid >> 5) & 1;
    const int n0 = blockIdx.x * 128;

    const int a_mrow = (lane & 15);
    const int a_ch = lane >> 4;
    const int b_nrow = (lane & 7) + ((lane >> 4) << 3);
    const int b_ch = (lane >> 3) & 1;

    float acc[2][8][4];
#pragma unroll
    for (int i = 0; i < 2; i++)
#pragma unroll
        for (int j = 0; j < 8; j++)
#pragma unroll
            for (int c = 0; c < 4; c++) acc[i][j][c] = 0.f;

    float4 breg[4];
    auto ldB = [&](int k0) {
#pragma unroll
        for (int i = 0; i < 4; ++i) {
            int idx = tid + i * 256;
            int row = n0 + (idx >> 3);
            int col = (idx & 7) << 2;
            breg[i] = *(const float4 *)(B + (size_t)row * 2048 + k0 + col);
        }
    };
    auto stB = [&](int st) {
#pragma unroll
        for (int i = 0; i < 4; ++i) {
            int idx = tid + i * 256;
            int row = idx >> 3;
            int colf = (idx & 7) << 2;
            int boff = colf * 2;
            int ch = boff >> 4;
            int inner = boff & 15;
            uint32_t off = (uint32_t)st * FC_STAGE_B + 16384 + row * 64 +
                           ((uint32_t)(ch ^ ((row >> 1) & 3)) << 4) + inner;
            __nv_bfloat16 h0, h1, h2, h3, l0, l1, l2, l3;
            splitf(breg[i].x, h0, l0); splitf(breg[i].y, h1, l1);
            splitf(breg[i].z, h2, l2); splitf(breg[i].w, h3, l3);
            *(__nv_bfloat162 *)(smem + off)        = __halves2bfloat162(h0, h1);
            *(__nv_bfloat162 *)(smem + off + 4)    = __halves2bfloat162(h2, h3);
            *(__nv_bfloat162 *)(smem + off + 8192) = __halves2bfloat162(l0, l1);
            *(__nv_bfloat162 *)(smem + off + 8196) = __halves2bfloat162(l2, l3);
        }
    };
    auto cpA = [&](int st, int k0) {
#pragma unroll
        for (int i = 0; i < 2; ++i) {
            int idx = tid + i * 256;
            int row = idx >> 2;
            int ch = idx & 3;
            uint32_t so = (uint32_t)st * FC_STAGE_B + row * 64 +
                          ((uint32_t)(ch ^ ((row >> 1) & 3)) << 4);
            size_t go = (size_t)row * 2048 + k0 + ch * 8;
            CPASYNC16(sb + so, Ahi + go);
            CPASYNC16(sb + 8192 + so, Alo + go);
        }
        CPCOMMIT;
    };

    cpA(0, 0);
    cpA(1, 32);
    ldB(0);
    stB(0);
    ldB(32);

    const int nk = 2048 / 32;
    for (int kt = 0; kt < nk; ++kt) {
        if (kt < nk - 1) { CPWAIT1; } else { CPWAIT0; }
        __syncthreads();
        if (kt + 1 < nk) stB((kt + 1) % 3);
        if (kt + 2 < nk) {
            ldB((kt + 2) * 32);
            cpA((kt + 2) % 3, (kt + 2) * 32);
        }
        const uint32_t csb = sb + (uint32_t)(kt % 3) * FC_STAGE_B;
#pragma unroll
        for (int kk = 0; kk < 32; kk += 16) {
            uint32_t ah[2][4], al[2][4];
#pragma unroll
            for (int fm = 0; fm < 2; ++fm) {
                int rowb = wm * 32 + fm * 16 + a_mrow;
                uint32_t sw = (uint32_t)(((kk >> 3) + a_ch) ^ ((rowb >> 1) & 3));
                uint32_t ad = csb + rowb * 64 + (sw << 4);
                ldsm4(ah[fm][0], ah[fm][1], ah[fm][2], ah[fm][3], ad);
                ldsm4(al[fm][0], al[fm][1], al[fm][2], al[fm][3], ad + 8192);
            }
#pragma unroll
            for (int fnp = 0; fnp < 4; ++fnp) {
                uint32_t bh[4], bl[4];
                int nrow = wn * 64 + fnp * 16 + b_nrow;
                uint32_t sw = (uint32_t)(((kk >> 3) + b_ch) ^ ((nrow >> 1) & 3));
                uint32_t bd = csb + 16384 + nrow * 64 + (sw << 4);
                ldsm4(bh[0], bh[1], bh[2], bh[3], bd);
                ldsm4(bl[0], bl[1], bl[2], bl[3], bd + 8192);
#pragma unroll
                for (int fm = 0; fm < 2; ++fm) {
                    float *d0 = acc[fm][fnp * 2];
                    float *d1 = acc[fm][fnp * 2 + 1];
                    MMA16816(d0, ah[fm][0], ah[fm][1], ah[fm][2], ah[fm][3], bh[0], bh[1]);
                    MMA16816(d0, ah[fm][0], ah[fm][1], ah[fm][2], ah[fm][3], bl[0], bl[1]);
                    MMA16816(d0, al[fm][0], al[fm][1], al[fm][2], al[fm][3], bh[0], bh[1]);
                    MMA16816(d1, ah[fm][0], ah[fm][1], ah[fm][2], ah[fm][3], bh[2], bh[3]);
                    MMA16816(d1, ah[fm][0], ah[fm][1], ah[fm][2], ah[fm][3], bl[2], bl[3]);
                    MMA16816(d1, al[fm][0], al[fm][1], al[fm][2], al[fm][3], bh[2], bh[3]);
                }
            }
        }
    }
#pragma unroll
    for (int fm = 0; fm < 2; ++fm)
#pragma unroll
        for (int fn = 0; fn < 8; ++fn) {
            int row = wm * 32 + fm * 16 + gid;
            int col = n0 + wn * 64 + fn * 8 + (t4 << 1);
            float b0 = bias[col], b1 = bias[col + 1];
            C[(size_t)row * CV + col]           = acc[fm][fn][0] + b0;
            C[(size_t)row * CV + col + 1]       = acc[fm][fn][1] + b1;
            C[(size_t)(row + 8) * CV + col]     = acc[fm][fn][2] + b0;
            C[(size_t)(row + 8) * CV + col + 1] = acc[fm][fn][3] + b1;
        }
}

// ---------------- fused energy GEMM + tanh + v-dot -> score[B,S] -------------
#define AS_STAGE_B 32768
#define ATTN_SMEM_BYTES (3 * AS_STAGE_B + 512)

__global__ __launch_bounds__(256, 2) void attn_score_kernel(const float *__restrict__ v) {
    extern __shared__ __align__(16) char smem[];
    const uint32_t sb = s2u(smem);
    float *red = (float *)(smem + 3 * AS_STAGE_B);

    const int b = blockIdx.y;
    const int n0 = blockIdx.x * 128;
    const int tid = threadIdx.x;
    const int lane = tid & 31;
    const int gid = lane >> 2;
    const int t4 = lane & 3;
    const int wm = (tid >> 5) >> 1;
    const int wn = (tid >> 5) & 1;
    if (tid < 128) red[tid] = 0.f;

    const int a_mrow = (lane & 15);
    const int a_ch = lane >> 4;
    const int b_nrow = (lane & 7) + ((lane >> 4) << 3);
    const int b_ch = (lane >> 3) & 1;

    const int ld_row = tid >> 2;
    const int ld_ch = tid & 3;

    float acc[2][8][4];
#pragma unroll
    for (int i = 0; i < 2; i++)
#pragma unroll
        for (int j = 0; j < 8; j++)
#pragma unroll
            for (int c = 0; c < 4; c++) acc[i][j][c] = 0.f;

#define LOAD_STAGE(st, k0)                                                     \
    do {                                                                       \
        _Pragma("unroll") for (int i = 0; i < 2; ++i) {                        \
            int row = ld_row + i * 64;                                         \
            uint32_t so = (uint32_t)(st) * AS_STAGE_B + row * 64 +             \
                          ((uint32_t)(ld_ch ^ ((row >> 1) & 3)) << 4);         \
            size_t goA = (size_t)(b * 128 + row) * CH + (k0) + ld_ch * 8;      \
            size_t goB = (size_t)(n0 + row) * CH + (k0) + ld_ch * 8;           \
            CPASYNC16(sb + so, g_enc_hi + goA);                                \
            CPASYNC16(sb + 8192 + so, g_enc_lo + goA);                         \
            CPASYNC16(sb + 16384 + so, g_w2_hi + goB);                         \
            CPASYNC16(sb + 24576 + so, g_w2_lo + goB);                         \
        }                                                                      \
        CPCOMMIT;                                                              \
    } while (0)

    LOAD_STAGE(0, 0);
    LOAD_STAGE(1, 32);
    for (int kt = 0; kt < 32; ++kt) {
        if (kt < 31) { CPWAIT1; } else { CPWAIT0; }
        __syncthreads();
        if (kt + 2 < 32) LOAD_STAGE((kt + 2) % 3, (kt + 2) * 32);
        const uint32_t csb = sb + (uint32_t)(kt % 3) * AS_STAGE_B;
#pragma unroll
        for (int kk = 0; kk < 32; kk += 16) {
            uint32_t ah[2][4], al[2][4];
#pragma unroll
            for (int fm = 0; fm < 2; ++fm) {
                int rowb = wm * 32 + fm * 16 + a_mrow;
                uint32_t sw = (uint32_t)(((kk >> 3) + a_ch) ^ ((rowb >> 1) & 3));
                uint32_t ad = csb + rowb * 64 + (sw << 4);
                ldsm4(ah[fm][0], ah[fm][1], ah[fm][2], ah[fm][3], ad);
                ldsm4(al[fm][0], al[fm][1], al[fm][2], al[fm][3], ad + 8192);
            }
#pragma unroll
            for (int fnp = 0; fnp < 4; ++fnp) {
                uint32_t bh[4], bl[4];
                int nrow = wn * 64 + fnp * 16 + b_nrow;
                uint32_t sw = (uint32_t)(((kk >> 3) + b_ch) ^ ((nrow >> 1) & 3));
                uint32_t bd = csb + 16384 + nrow * 64 + (sw << 4);
                ldsm4(bh[0], bh[1], bh[2], bh[3], bd);
                ldsm4(bl[0], bl[1], bl[2], bl[3], bd + 8192);
#pragma unroll
                for (int fm = 0; fm < 2; ++fm) {
                    float *d0 = acc[fm][fnp * 2];
                    float *d1 = acc[fm][fnp * 2 + 1];
                    MMA16816(d0, ah[fm][0], ah[fm][1], ah[fm][2], ah[fm][3], bh[0], bh[1]);
                    MMA16816(d0, ah[fm][0], ah[fm][1], ah[fm][2], ah[fm][3], bl[0], bl[1]);
                    MMA16816(d0, al[fm][0], al[fm][1], al[fm][2], al[fm][3], bh[0], bh[1]);
                    MMA16816(d1, ah[fm][0], ah[fm][1], ah[fm][2], ah[fm][3], bh[2], bh[3]);
                    MMA16816(d1, ah[fm][0], ah[fm][1], ah[fm][2], ah[fm][3], bl[2], bl[3]);
                    MMA16816(d1, al[fm][0], al[fm][1], al[fm][2], al[fm][3], bh[2], bh[3]);
                }
            }
        }
    }
    __syncthreads();

    const float *hWb = g_hW + (size_t)b * CH;
    float pA[2] = {0.f, 0.f}, pB[2] = {0.f, 0.f};
#pragma unroll
    for (int fm = 0; fm < 2; ++fm)
#pragma unroll
        for (int fn = 0; fn < 8; ++fn) {
            int col = n0 + wn * 64 + fn * 8 + (t4 << 1);
            float hw0 = hWb[col], hw1 = hWb[col + 1];
            float v0 = v[col], v1 = v[col + 1];
            pA[fm] += tanhf(acc[fm][fn][0] + hw0) * v0 +
                      tanhf(acc[fm][fn][1] + hw1) * v1;
            pB[fm] += tanhf(acc[fm][fn][2] + hw0) * v0 +
                      tanhf(acc[fm][fn][3] + hw1) * v1;
        }
#pragma unroll
    for (int fm = 0; fm < 2; ++fm)
#pragma unroll
        for (int j = 0; j < 2; ++j) {
            float val = j ? pB[fm] : pA[fm];
            val += __shfl_xor_sync(0xffffffffu, val, 1);
            val += __shfl_xor_sync(0xffffffffu, val, 2);
            if (t4 == 0) atomicAdd(&red[wm * 32 + fm * 16 + j * 8 + gid], val);
        }
    __syncthreads();
    if (tid < 128) atomicAdd(&g_score[b * 128 + tid], red[tid]);
}

// ---------------- context (+inline softmax) + assemble xin -------------------
// grid (128, 4): b x H-quadrant. Software-pipelined 8-deep prefetch of enc
// (explicit MLP; the naive unrolled loop measured MLP ~1 -> 33.7us).
__global__ __launch_bounds__(256) void context_kernel(
    const int *__restrict__ x, const float *__restrict__ emb_table,
    const float *__restrict__ hidden, const float *__restrict__ enc,
    float *__restrict__ out_attn) {
    const int b = blockIdx.x;
    const int q = blockIdx.y;
    const int t = threadIdx.x;
    __shared__ float w_s[128];
    __shared__ float r_s[128];
    // inline softmax over 128 raw scores
    if (t < 128) {
        float s = g_score[b * 128 + t];
        w_s[t] = s;
        r_s[t] = s;
    }
    __syncthreads();
#pragma unroll
    for (int st = 64; st > 0; st >>= 1) {
        if (t < st) r_s[t] = fmaxf(r_s[t], r_s[t + st]);
        __syncthreads();
    }
    float mx = r_s[0];
    __syncthreads();
    if (t < 128) r_s[t] = expf(w_s[t] - mx);
    __syncthreads();
    float e_t = (t < 128) ? r_s[t] : 0.f;
#pragma unroll
    for (int st = 64; st > 0; st >>= 1) {
        if (t < st) r_s[t] += r_s[t + st];
        __syncthreads();
    }
    float inv = 1.0f / r_s[0];
    __syncthreads();
    if (t < 128) {
        float w = e_t * inv;
        w_s[t] = w;
        if (q == 0) out_attn[b * 128 + t] = w;
    }

    const int h = q * 256 + t;
    if (q < 2) {
        int i = q * 256 + t;
        __nv_bfloat16 hi, lo;
        splitf(emb_table[(size_t)x[b] * CE + i], hi, lo);
        g_xin_hi[(size_t)b * 2560 + i] = hi;
        g_xin_lo[(size_t)b * 2560 + i] = lo;
    }
    {
        __nv_bfloat16 hi, lo;
        splitf(hidden[(size_t)b * CH + h], hi, lo);
        g_xin_hi[(size_t)b * 2560 + 1536 + h] = hi;
        g_xin_lo[(size_t)b * 2560 + 1536 + h] = lo;
    }
    __syncthreads();

    // context dot product with explicit 8-deep prefetch double buffer
    const float *encb = enc + (size_t)b * CS * CH + h;
    float acc = 0.f;
    float vbuf[8];
#pragma unroll
    for (int i = 0; i < 8; ++i) vbuf[i] = __ldcs(encb + (size_t)i * CH);
    for (int s0 = 0; s0 < CS; s0 += 8) {
        float cur[8];
#pragma unroll
        for (int i = 0; i < 8; ++i) cur[i] = vbuf[i];
        if (s0 + 8 < CS) {
#pragma unroll
            for (int i = 0; i < 8; ++i)
                vbuf[i] = __ldcs(encb + (size_t)(s0 + 8 + i) * CH);
        }
#pragma unroll
        for (int i = 0; i < 8; ++i) acc += w_s[s0 + i] * cur[i];
    }

    __nv_bfloat16 hi, lo;
    splitf(acc, hi, lo);
    g_xin_hi[(size_t)b * 2560 + 512 + h] = hi;
    g_xin_lo[(size_t)b * 2560 + 512 + h] = lo;
    g_out2_hi[(size_t)b * 2048 + 1024 + h] = hi;
    g_out2_lo[(size_t)b * 2048 + 1024 + h] = lo;
}

// ---------------- LSTM pointwise ---------------------------------------------
__global__ __launch_bounds__(256) void lstm_kernel(
    const float *__restrict__ cell, float *__restrict__ out_h,
    float *__restrict__ out_c) {
    int id = blockIdx.x * 256 + threadIdx.x;
    int b = id >> 10;
    int h = id & 1023;
    const float *gt = g_gates + (size_t)b * 4096;
    float gi = gt[h], gf = gt[1024 + h], gg = gt[2048 + h], go = gt[3072 + h];
    float c_old = cell[(size_t)b * CH + h];
    float cn = sigf(gf) * c_old + sigf(gi) * tanhf(gg);
    float hn = sigf(go) * tanhf(cn);
    out_h[(size_t)b * CH + h] = hn;
    out_c[(size_t)b * CH + h] = cn;
    __nv_bfloat16 hi, lo;
    splitf(hn, hi, lo);
    g_out2_hi[(size_t)b * 2048 + h] = hi;
    g_out2_lo[(size_t)b * 2048 + h] = lo;
}

// ---------------- launch ------------------------------------------------------
extern "C" void kernel_launch(void *const *d_in, const int *in_sizes, int n_in,
                              void *d_out, int out_size) {
    (void)in_sizes; (void)n_in; (void)out_size;
    const int *x           = (const int *)d_in[0];
    const float *hidden    = (const float *)d_in[1];
    const float *cell      = (const float *)d_in[2];
    const float *enc       = (const float *)d_in[3];
    const float *emb_table = (const float *)d_in[4];
    const float *attn_W    = (const float *)d_in[5];
    const float *attn_b    = (const float *)d_in[6];
    const float *v         = (const float *)d_in[7];
    const float *W_ih      = (const float *)d_in[8];
    const float *W_hh      = (const float *)d_in[9];
    const float *b_ih      = (const float *)d_in[10];
    const float *b_hh      = (const float *)d_in[11];
    const float *fc_W      = (const float *)d_in[12];
    const float *fc_b      = (const float *)d_in[13];

    float *out        = (float *)d_out;
    float *out_logits = out;
    float *out_h      = out + (size_t)CB * CV;
    float *out_c      = out_h + (size_t)CB * CH;
    float *out_attn   = out_c + (size_t)CB * CH;

    float *gatesp = nullptr;
    __nv_bfloat16 *o2h = nullptr, *o2l = nullptr, *xih = nullptr, *xil = nullptr;
    cudaGetSymbolAddress((void **)&gatesp, g_gates);
    cudaGetSymbolAddress((void **)&o2h, g_out2_hi);
    cudaGetSymbolAddress((void **)&o2l, g_out2_lo);
    cudaGetSymbolAddress((void **)&xih, g_xin_hi);
    cudaGetSymbolAddress((void **)&xil, g_xin_lo);

    cudaFuncSetAttribute(attn_score_kernel,
                         cudaFuncAttributeMaxDynamicSharedMemorySize,
                         ATTN_SMEM_BYTES);
    cudaFuncSetAttribute(gemm2_kernel,
                         cudaFuncAttributeMaxDynamicSharedMemorySize,
                         G2_SMEM_BYTES);
    cudaFuncSetAttribute(fc_kernel,
                         cudaFuncAttributeMaxDynamicSharedMemorySize,
                         FC_SMEM_BYTES);

    // 1) merged: split enc + split attn_W[:,H:2H] + zero score + seed biases
    conv_all_kernel<<<16384, 256>>>(enc, attn_W, attn_b, b_ih, b_hh);
    // 2) hW += h_last @ attn_W[:, :H]^T  (K-split x4, atomic)
    hw_kernel<<<dim3(64, 4), 256>>>(hidden, attn_W);
    // 3) fused energy GEMM + tanh + v-dot -> raw g_score
    attn_score_kernel<<<dim3(8, CB), 256, ATTN_SMEM_BYTES>>>(v);
    // 4) context (+inline softmax) + xin assembly (launch #4: profiled)
    context_kernel<<<dim3(CB, 4), 256>>>(x, emb_table, hidden, enc, out_attn);
    // 5) gates += xin @ [W_ih|W_hh]^T  (single launch, K-split via grid.y)
    gemm2_kernel<<<dim3(4096 / 64, 4), 256, G2_SMEM_BYTES>>>(
        xih, xil, 2560,
        W_ih, 1536, 1536, W_hh, CH,
        nullptr, gatesp, 4096, 640, 1);
    // 6) LSTM pointwise
    lstm_kernel<<<(CB * CH) / 256, 256>>>(cell, out_h, out_c);
    // 7) logits = [h_new|context] @ fc_W^T + fc_b
    fc_kernel<<<CV / 128, 256, FC_SMEM_BYTES>>>(o2h, o2l, fc_W, fc_b, out_logits);
}

// round 14
// speedup vs baseline: 1.1060x; 1.0100x over previous
#include <cuda_runtime.h>
#include <cuda_bf16.h>
#include <stdint.h>
#include <math.h>

#define CB 128
#define CS 128
#define CH 1024
#define CE 512
#define CV 32000

// ---------------- scratch (__device__ globals; no allocations allowed) -------
__device__ __align__(16) float g_hW4[4][CB * CH];  // per-K-chunk partials of hW
__device__ __align__(16) float g_score[CB * CS];   // raw scores
__device__ __align__(16) float g_gates[CB * 4096];
__device__ __align__(16) __nv_bfloat16 g_xin_hi[CB * 2560];   // [emb|context|h_last]
__device__ __align__(16) __nv_bfloat16 g_xin_lo[CB * 2560];
__device__ __align__(16) __nv_bfloat16 g_out2_hi[CB * 2048];  // [h_new | context]
__device__ __align__(16) __nv_bfloat16 g_out2_lo[CB * 2048];
__device__ __align__(16) __nv_bfloat16 g_enc_hi[CB * CS * CH];
__device__ __align__(16) __nv_bfloat16 g_enc_lo[CB * CS * CH];
__device__ __align__(16) __nv_bfloat16 g_w2_hi[CH * CH];      // attn_W[:, H:2H] as [n][k]
__device__ __align__(16) __nv_bfloat16 g_w2_lo[CH * CH];

// ---------------- helpers ----------------------------------------------------
__device__ __forceinline__ void splitf(float x, __nv_bfloat16 &hi, __nv_bfloat16 &lo) {
    hi = __float2bfloat16_rn(x);
    lo = __float2bfloat16_rn(x - __bfloat162float(hi));
}
__device__ __forceinline__ float sigf(float x) { return 1.0f / (1.0f + expf(-x)); }
__device__ __forceinline__ uint32_t s2u(const void *p) {
    return (uint32_t)__cvta_generic_to_shared(p);
}
__device__ __forceinline__ void ldsm4(uint32_t &r0, uint32_t &r1, uint32_t &r2,
                                      uint32_t &r3, uint32_t addr) {
    asm volatile("ldmatrix.sync.aligned.m8n8.x4.shared.b16 {%0,%1,%2,%3}, [%4];"
                 : "=r"(r0), "=r"(r1), "=r"(r2), "=r"(r3)
                 : "r"(addr));
}

#define MMA16816(d, a0, a1, a2, a3, b0, b1)                                    \
    asm volatile(                                                              \
        "mma.sync.aligned.m16n8k16.row.col.f32.bf16.bf16.f32 "                 \
        "{%0,%1,%2,%3},{%4,%5,%6,%7},{%8,%9},{%0,%1,%2,%3};\n"                 \
        : "+f"(d[0]), "+f"(d[1]), "+f"(d[2]), "+f"(d[3])                       \
        : "r"(a0), "r"(a1), "r"(a2), "r"(a3), "r"(b0), "r"(b1))

#define CPASYNC16(dst, src)                                                    \
    asm volatile("cp.async.cg.shared.global [%0], [%1], 16;\n" ::"r"(dst),     \
                 "l"(src))
#define CPCOMMIT asm volatile("cp.async.commit_group;\n" ::)
#define CPWAIT1 asm volatile("cp.async.wait_group 1;\n" ::)
#define CPWAIT0 asm volatile("cp.async.wait_group 0;\n" ::)

// ---------------- merged: hw GEMM (blocks 0..255) + splits/init (256..16639) -
// hw blocks run FIRST (low indices), overlapping the DRAM-bound conv phase.
// hw: per-K-chunk partials into g_hW4[kq] (plain stores, race-free).
__global__ __launch_bounds__(256) void conv_hw_kernel(
    const float *__restrict__ enc, const float *__restrict__ attn_W,
    const float *__restrict__ b_ih, const float *__restrict__ b_hh,
    const float *__restrict__ hidden) {
    __shared__ float Hs[128][65];
    __shared__ float Ws[16][65];
    const int tid = threadIdx.x;

    if (blockIdx.x < 256) {
        // ---- hw GEMM block: hW4[kq] = hidden @ attn_W[:, :H]^T (K-chunk kq)
        const int n0 = (blockIdx.x & 63) * 16;
        const int kq = blockIdx.x >> 6;
        const int kbase = kq * 256;
        const int bt = tid & 63;
        const int nt = tid >> 6;
        float acc[2][4] = {{0.f, 0.f, 0.f, 0.f}, {0.f, 0.f, 0.f, 0.f}};

        for (int kc = 0; kc < 4; ++kc) {
            const int k0 = kbase + kc * 64;
#pragma unroll
            for (int i = 0; i < 8; ++i) {
                int idx = tid + 256 * i;
                int row = idx >> 4;
                int cv = (idx & 15) << 2;
                float4 v4 = *(const float4 *)(hidden + (size_t)row * CH + k0 + cv);
                Hs[row][cv] = v4.x; Hs[row][cv + 1] = v4.y;
                Hs[row][cv + 2] = v4.z; Hs[row][cv + 3] = v4.w;
            }
            {
                int row = tid >> 4;
                int cv = (tid & 15) << 2;
                float4 v4 = *(const float4 *)(attn_W + (size_t)(n0 + row) * 2048 + k0 + cv);
                Ws[row][cv] = v4.x; Ws[row][cv + 1] = v4.y;
                Ws[row][cv + 2] = v4.z; Ws[row][cv + 3] = v4.w;
            }
            __syncthreads();
#pragma unroll 8
            for (int k = 0; k < 64; ++k) {
                float w0 = Ws[nt * 4 + 0][k], w1 = Ws[nt * 4 + 1][k];
                float w2 = Ws[nt * 4 + 2][k], w3 = Ws[nt * 4 + 3][k];
                float h0 = Hs[bt * 2 + 0][k], h1 = Hs[bt * 2 + 1][k];
                acc[0][0] += h0 * w0; acc[0][1] += h0 * w1;
                acc[0][2] += h0 * w2; acc[0][3] += h0 * w3;
                acc[1][0] += h1 * w0; acc[1][1] += h1 * w1;
                acc[1][2] += h1 * w2; acc[1][3] += h1 * w3;
            }
            __syncthreads();
        }
#pragma unroll
        for (int i = 0; i < 2; ++i)
#pragma unroll
            for (int j = 0; j < 4; ++j) {
                int n = n0 + nt * 4 + j;
                g_hW4[kq][(size_t)(bt * 2 + i) * CH + n] = acc[i][j];
            }
        return;
    }

    // ---- conv block
    const int cx = blockIdx.x - 256;  // 0..16383
    size_t idx = (size_t)cx * 256 + tid;  // float4 index over enc
    float4 v4 = ((const float4 *)enc)[idx];
    __nv_bfloat16 h0, h1, h2, h3, l0, l1, l2, l3;
    splitf(v4.x, h0, l0); splitf(v4.y, h1, l1);
    splitf(v4.z, h2, l2); splitf(v4.w, h3, l3);
    ((__nv_bfloat162 *)g_enc_hi)[idx * 2 + 0] = __halves2bfloat162(h0, h1);
    ((__nv_bfloat162 *)g_enc_hi)[idx * 2 + 1] = __halves2bfloat162(h2, h3);
    ((__nv_bfloat162 *)g_enc_lo)[idx * 2 + 0] = __halves2bfloat162(l0, l1);
    ((__nv_bfloat162 *)g_enc_lo)[idx * 2 + 1] = __halves2bfloat162(l2, l3);

    if (cx >= 1024) return;
    if (cx < 64) g_score[cx * 256 + tid] = 0.f;
    {
        int i2 = (cx * 256 + tid) * 2;
        g_gates[i2]     = b_ih[i2 & 4095] + b_hh[i2 & 4095];
        g_gates[i2 + 1] = b_ih[(i2 + 1) & 4095] + b_hh[(i2 + 1) & 4095];
    }
    size_t idx2 = (size_t)cx * 256 + tid;  // 262144 float4s of w2
    int n = (int)(idx2 >> 8);
    int k = (int)(idx2 & 255) << 2;
    float4 w4 = *(const float4 *)(attn_W + (size_t)n * 2048 + 1024 + k);
    splitf(w4.x, h0, l0); splitf(w4.y, h1, l1);
    splitf(w4.z, h2, l2); splitf(w4.w, h3, l3);
    size_t o = ((size_t)n * CH + k) >> 1;
    ((__nv_bfloat162 *)g_w2_hi)[o + 0] = __halves2bfloat162(h0, h1);
    ((__nv_bfloat162 *)g_w2_hi)[o + 1] = __halves2bfloat162(h2, h3);
    ((__nv_bfloat162 *)g_w2_lo)[o + 0] = __halves2bfloat162(l0, l1);
    ((__nv_bfloat162 *)g_w2_lo)[o + 1] = __halves2bfloat162(l2, l3);
}

// ---------------- pipelined bf16-split x3 GEMM (gates) -----------------------
#define A2_STAGE (128 * 40)
#define B2_STAGE (64 * 40)
#define G2_SMEM_BYTES (3 * (A2_STAGE + B2_STAGE) * 2 * 2)

__global__ __launch_bounds__(256, 2) void gemm2_kernel(
    const __nv_bfloat16 *__restrict__ Ahi, const __nv_bfloat16 *__restrict__ Alo,
    int lda,
    const float *__restrict__ B1, int ldb1, int ksw,
    const float *__restrict__ B2, int ldb2,
    const float *__restrict__ bias1,
    float *__restrict__ C, int ldc, int K, int atomic_out) {
    extern __shared__ __align__(16) __nv_bfloat16 sm2[];
    __nv_bfloat16 *AsHi = sm2;
    __nv_bfloat16 *AsLo = AsHi + 3 * A2_STAGE;
    __nv_bfloat16 *BsHi = AsLo + 3 * A2_STAGE;
    __nv_bfloat16 *BsLo = BsHi + 3 * B2_STAGE;

    const int tid = threadIdx.x;
    const int lane = tid & 31;
    const int gid = lane >> 2;
    const int t4 = lane & 3;
    const int wm = (tid >> 5) >> 1;
    const int wn = (tid >> 5) & 1;
    const int n0 = blockIdx.x * 64;
    const int kbase = blockIdx.y * K;

    const int a_mrow = (lane & 15);
    const int a_koff = (lane >> 4) << 3;
    const int b_nrow = (lane & 7) + ((lane >> 4) << 3);
    const int b_koff = ((lane >> 3) & 1) << 3;

    const int nk = K >> 5;

    float acc[2][4][4];
#pragma unroll
    for (int i = 0; i < 2; i++)
#pragma unroll
        for (int j = 0; j < 4; j++)
#pragma unroll
            for (int c = 0; c < 4; c++) acc[i][j][c] = 0.f;

    float4 breg[2];
    auto ldB = [&](int k0) {
#pragma unroll
        for (int i = 0; i < 2; ++i) {
            int idx = tid + i * 256;
            int row = n0 + (idx >> 3);
            int k = kbase + k0 + ((idx & 7) << 2);
            const float *src = (k < ksw) ? (B1 + (size_t)row * ldb1 + k)
                                         : (B2 + (size_t)row * ldb2 + (k - ksw));
            breg[i] = *(const float4 *)src;
        }
    };
    auto stB = [&](int st) {
#pragma unroll
        for (int i = 0; i < 2; ++i) {
            int idx = tid + i * 256;
            int row = idx >> 3;
            int col = (idx & 7) << 2;
            __nv_bfloat16 h0, h1, h2, h3, l0, l1, l2, l3;
            splitf(breg[i].x, h0, l0); splitf(breg[i].y, h1, l1);
            splitf(breg[i].z, h2, l2); splitf(breg[i].w, h3, l3);
            __nv_bfloat16 *dh = BsHi + st * B2_STAGE + row * 40 + col;
            __nv_bfloat16 *dl = BsLo + st * B2_STAGE + row * 40 + col;
            *(__nv_bfloat162 *)dh       = __halves2bfloat162(h0, h1);
            *(__nv_bfloat162 *)(dh + 2) = __halves2bfloat162(h2, h3);
            *(__nv_bfloat162 *)dl       = __halves2bfloat162(l0, l1);
            *(__nv_bfloat162 *)(dl + 2) = __halves2bfloat162(l2, l3);
        }
    };
    auto cpA = [&](int st, int k0) {
#pragma unroll
        for (int i = 0; i < 2; ++i) {
            int idx = tid + i * 256;
            int row = idx >> 2;
            int col = (idx & 3) << 3;
            uint32_t dof = st * A2_STAGE + row * 40 + col;
            size_t go = (size_t)row * lda + kbase + k0 + col;
            CPASYNC16(s2u(AsHi + dof), Ahi + go);
            CPASYNC16(s2u(AsLo + dof), Alo + go);
        }
        CPCOMMIT;
    };

    cpA(0, 0);
    if (nk > 1) cpA(1, 32);
    ldB(0);
    stB(0);
    if (nk > 1) ldB(32);

    for (int kt = 0; kt < nk; ++kt) {
        if (kt < nk - 1) { CPWAIT1; } else { CPWAIT0; }
        __syncthreads();
        if (kt + 1 < nk) stB((kt + 1) % 3);
        if (kt + 2 < nk) {
            ldB((kt + 2) * 32);
            cpA((kt + 2) % 3, (kt + 2) * 32);
        }
        const int st = kt % 3;
        const __nv_bfloat16 *cAH = AsHi + st * A2_STAGE;
        const __nv_bfloat16 *cAL = AsLo + st * A2_STAGE;
        const __nv_bfloat16 *cBH = BsHi + st * B2_STAGE;
        const __nv_bfloat16 *cBL = BsLo + st * B2_STAGE;
#pragma unroll
        for (int kk = 0; kk < 32; kk += 16) {
            uint32_t ah[2][4], al[2][4];
#pragma unroll
            for (int fm = 0; fm < 2; ++fm) {
                int rowb = wm * 32 + fm * 16 + a_mrow;
                ldsm4(ah[fm][0], ah[fm][1], ah[fm][2], ah[fm][3],
                      s2u(cAH + rowb * 40 + kk + a_koff));
                ldsm4(al[fm][0], al[fm][1], al[fm][2], al[fm][3],
                      s2u(cAL + rowb * 40 + kk + a_koff));
            }
#pragma unroll
            for (int fnp = 0; fnp < 2; ++fnp) {
                uint32_t bh[4], bl[4];
                int nrow = wn * 32 + fnp * 16 + b_nrow;
                ldsm4(bh[0], bh[1], bh[2], bh[3],
                      s2u(cBH + nrow * 40 + kk + b_koff));
                ldsm4(bl[0], bl[1], bl[2], bl[3],
                      s2u(cBL + nrow * 40 + kk + b_koff));
#pragma unroll
                for (int fm = 0; fm < 2; ++fm) {
                    float *d0 = acc[fm][fnp * 2];
                    float *d1 = acc[fm][fnp * 2 + 1];
                    MMA16816(d0, ah[fm][0], ah[fm][1], ah[fm][2], ah[fm][3], bh[0], bh[1]);
                    MMA16816(d0, ah[fm][0], ah[fm][1], ah[fm][2], ah[fm][3], bl[0], bl[1]);
                    MMA16816(d0, al[fm][0], al[fm][1], al[fm][2], al[fm][3], bh[0], bh[1]);
                    MMA16816(d1, ah[fm][0], ah[fm][1], ah[fm][2], ah[fm][3], bh[2], bh[3]);
                    MMA16816(d1, ah[fm][0], ah[fm][1], ah[fm][2], ah[fm][3], bl[2], bl[3]);
                    MMA16816(d1, al[fm][0], al[fm][1], al[fm][2], al[fm][3], bh[2], bh[3]);
                }
            }
        }
    }
#pragma unroll
    for (int fm = 0; fm < 2; ++fm)
#pragma unroll
        for (int fn = 0; fn < 4; ++fn) {
            int row = wm * 32 + fm * 16 + gid;
            int col = n0 + wn * 32 + fn * 8 + (t4 << 1);
            if (atomic_out) {
                atomicAdd(&C[(size_t)row * ldc + col], acc[fm][fn][0]);
                atomicAdd(&C[(size_t)row * ldc + col + 1], acc[fm][fn][1]);
                atomicAdd(&C[(size_t)(row + 8) * ldc + col], acc[fm][fn][2]);
                atomicAdd(&C[(size_t)(row + 8) * ldc + col + 1], acc[fm][fn][3]);
            } else {
                float b0 = bias1 ? bias1[col] : 0.f;
                float b1 = bias1 ? bias1[col + 1] : 0.f;
                C[(size_t)row * ldc + col]           = acc[fm][fn][0] + b0;
                C[(size_t)row * ldc + col + 1]       = acc[fm][fn][1] + b1;
                C[(size_t)(row + 8) * ldc + col]     = acc[fm][fn][2] + b0;
                C[(size_t)(row + 8) * ldc + col + 1] = acc[fm][fn][3] + b1;
            }
        }
}

// ---------------- FC GEMM: logits = out2 @ fc_W^T + fc_b ---------------------
#define FC_STAGE_B 32768
#define FC_SMEM_BYTES (3 * FC_STAGE_B)

__global__ __launch_bounds__(256, 2) void fc_kernel(
    const __nv_bfloat16 *__restrict__ Ahi, const __nv_bfloat16 *__restrict__ Alo,
    const float *__restrict__ B, const float *__restrict__ bias,
    float *__restrict__ C) {
    extern __shared__ __align__(16) char smem[];
    const uint32_t sb = s2u(smem);

    const int tid = threadIdx.x;
    const int lane = tid & 31;
    const int gid = lane >> 2;
    const int t4 = lane & 3;
    const int wm = (tid >> 5) >> 1;
    const int wn = (tid >> 5) & 1;
    const int n0 = blockIdx.x * 128;

    const int a_mrow = (lane & 15);
    const int a_ch = lane >> 4;
    const int b_nrow = (lane & 7) + ((lane >> 4) << 3);
    const int b_ch = (lane >> 3) & 1;

    float acc[2][8][4];
#pragma unroll
    for (int i = 0; i < 2; i++)
#pragma unroll
        for (int j = 0; j < 8; j++)
#pragma unroll
            for (int c = 0; c < 4; c++) acc[i][j][c] = 0.f;

    float4 breg[4];
    auto ldB = [&](int k0) {
#pragma unroll
        for (int i = 0; i < 4; ++i) {
            int idx = tid + i * 256;
            int row = n0 + (idx >> 3);
            int col = (idx & 7) << 2;
            breg[i] = *(const float4 *)(B + (size_t)row * 2048 + k0 + col);
        }
    };
    auto stB = [&](int st) {
#pragma unroll
        for (int i = 0; i < 4; ++i) {
            int idx = tid + i * 256;
            int row = idx >> 3;
            int colf = (idx & 7) << 2;
            int boff = colf * 2;
            int ch = boff >> 4;
            int inner = boff & 15;
            uint32_t off = (uint32_t)st * FC_STAGE_B + 16384 + row * 64 +
                           ((uint32_t)(ch ^ ((row >> 1) & 3)) << 4) + inner;
            __nv_bfloat16 h0, h1, h2, h3, l0, l1, l2, l3;
            splitf(breg[i].x, h0, l0); splitf(breg[i].y, h1, l1);
            splitf(breg[i].z, h2, l2); splitf(breg[i].w, h3, l3);
            *(__nv_bfloat162 *)(smem + off)        = __halves2bfloat162(h0, h1);
            *(__nv_bfloat162 *)(smem + off + 4)    = __halves2bfloat162(h2, h3);
            *(__nv_bfloat162 *)(smem + off + 8192) = __halves2bfloat162(l0, l1);
            *(__nv_bfloat162 *)(smem + off + 8196) = __halves2bfloat162(l2, l3);
        }
    };
    auto cpA = [&](int st, int k0) {
#pragma unroll
        for (int i = 0; i < 2; ++i) {
            int idx = tid + i * 256;
            int row = idx >> 2;
            int ch = idx & 3;
            uint32_t so = (uint32_t)st * FC_STAGE_B + row * 64 +
                          ((uint32_t)(ch ^ ((row >> 1) & 3)) << 4);
            size_t go = (size_t)row * 2048 + k0 + ch * 8;
            CPASYNC16(sb + so, Ahi + go);
            CPASYNC16(sb + 8192 + so, Alo + go);
        }
        CPCOMMIT;
    };

    cpA(0, 0);
    cpA(1, 32);
    ldB(0);
    stB(0);
    ldB(32);

    const int nk = 2048 / 32;
    for (int kt = 0; kt < nk; ++kt) {
        if (kt < nk - 1) { CPWAIT1; } else { CPWAIT0; }
        __syncthreads();
        if (kt + 1 < nk) stB((kt + 1) % 3);
        if (kt + 2 < nk) {
            ldB((kt + 2) * 32);
            cpA((kt + 2) % 3, (kt + 2) * 32);
        }
        const uint32_t csb = sb + (uint32_t)(kt % 3) * FC_STAGE_B;
#pragma unroll
        for (int kk = 0; kk < 32; kk += 16) {
            uint32_t ah[2][4], al[2][4];
#pragma unroll
            for (int fm = 0; fm < 2; ++fm) {
                int rowb = wm * 32 + fm * 16 + a_mrow;
                uint32_t sw = (uint32_t)(((kk >> 3) + a_ch) ^ ((rowb >> 1) & 3));
                uint32_t ad = csb + rowb * 64 + (sw << 4);
                ldsm4(ah[fm][0], ah[fm][1], ah[fm][2], ah[fm][3], ad);
                ldsm4(al[fm][0], al[fm][1], al[fm][2], al[fm][3], ad + 8192);
            }
#pragma unroll
            for (int fnp = 0; fnp < 4; ++fnp) {
                uint32_t bh[4], bl[4];
                int nrow = wn * 64 + fnp * 16 + b_nrow;
                uint32_t sw = (uint32_t)(((kk >> 3) + b_ch) ^ ((nrow >> 1) & 3));
                uint32_t bd = csb + 16384 + nrow * 64 + (sw << 4);
                ldsm4(bh[0], bh[1], bh[2], bh[3], bd);
                ldsm4(bl[0], bl[1], bl[2], bl[3], bd + 8192);
#pragma unroll
                for (int fm = 0; fm < 2; ++fm) {
                    float *d0 = acc[fm][fnp * 2];
                    float *d1 = acc[fm][fnp * 2 + 1];
                    MMA16816(d0, ah[fm][0], ah[fm][1], ah[fm][2], ah[fm][3], bh[0], bh[1]);
                    MMA16816(d0, ah[fm][0], ah[fm][1], ah[fm][2], ah[fm][3], bl[0], bl[1]);
                    MMA16816(d0, al[fm][0], al[fm][1], al[fm][2], al[fm][3], bh[0], bh[1]);
                    MMA16816(d1, ah[fm][0], ah[fm][1], ah[fm][2], ah[fm][3], bh[2], bh[3]);
                    MMA16816(d1, ah[fm][0], ah[fm][1], ah[fm][2], ah[fm][3], bl[2], bl[3]);
                    MMA16816(d1, al[fm][0], al[fm][1], al[fm][2], al[fm][3], bh[2], bh[3]);
                }
            }
        }
    }
#pragma unroll
    for (int fm = 0; fm < 2; ++fm)
#pragma unroll
        for (int fn = 0; fn < 8; ++fn) {
            int row = wm * 32 + fm * 16 + gid;
            int col = n0 + wn * 64 + fn * 8 + (t4 << 1);
            float b0 = bias[col], b1 = bias[col + 1];
            C[(size_t)row * CV + col]           = acc[fm][fn][0] + b0;
            C[(size_t)row * CV + col + 1]       = acc[fm][fn][1] + b1;
            C[(size_t)(row + 8) * CV + col]     = acc[fm][fn][2] + b0;
            C[(size_t)(row + 8) * CV + col + 1] = acc[fm][fn][3] + b1;
        }
}

// ---------------- fused energy GEMM + tanh + v-dot -> score[B,S] -------------
#define AS_STAGE_B 32768
#define ATTN_SMEM_BYTES (3 * AS_STAGE_B + 512)

__global__ __launch_bounds__(256, 2) void attn_score_kernel(
    const float *__restrict__ v, const float *__restrict__ attn_b) {
    extern __shared__ __align__(16) char smem[];
    const uint32_t sb = s2u(smem);
    float *red = (float *)(smem + 3 * AS_STAGE_B);

    const int b = blockIdx.y;
    const int n0 = blockIdx.x * 128;
    const int tid = threadIdx.x;
    const int lane = tid & 31;
    const int gid = lane >> 2;
    const int t4 = lane & 3;
    const int wm = (tid >> 5) >> 1;
    const int wn = (tid >> 5) & 1;
    if (tid < 128) red[tid] = 0.f;

    const int a_mrow = (lane & 15);
    const int a_ch = lane >> 4;
    const int b_nrow = (lane & 7) + ((lane >> 4) << 3);
    const int b_ch = (lane >> 3) & 1;

    const int ld_row = tid >> 2;
    const int ld_ch = tid & 3;

    float acc[2][8][4];
#pragma unroll
    for (int i = 0; i < 2; i++)
#pragma unroll
        for (int j = 0; j < 8; j++)
#pragma unroll
            for (int c = 0; c < 4; c++) acc[i][j][c] = 0.f;

#define LOAD_STAGE(st, k0)                                                     \
    do {                                                                       \
        _Pragma("unroll") for (int i = 0; i < 2; ++i) {                        \
            int row = ld_row + i * 64;                                         \
            uint32_t so = (uint32_t)(st) * AS_STAGE_B + row * 64 +             \
                          ((uint32_t)(ld_ch ^ ((row >> 1) & 3)) << 4);         \
            size_t goA = (size_t)(b * 128 + row) * CH + (k0) + ld_ch * 8;      \
            size_t goB = (size_t)(n0 + row) * CH + (k0) + ld_ch * 8;           \
            CPASYNC16(sb + so, g_enc_hi + goA);                                \
            CPASYNC16(sb + 8192 + so, g_enc_lo + goA);                         \
            CPASYNC16(sb + 16384 + so, g_w2_hi + goB);                         \
            CPASYNC16(sb + 24576 + so, g_w2_lo + goB);                         \
        }                                                                      \
        CPCOMMIT;                                                              \
    } while (0)

    LOAD_STAGE(0, 0);
    LOAD_STAGE(1, 32);
    for (int kt = 0; kt < 32; ++kt) {
        if (kt < 31) { CPWAIT1; } else { CPWAIT0; }
        __syncthreads();
        if (kt + 2 < 32) LOAD_STAGE((kt + 2) % 3, (kt + 2) * 32);
        const uint32_t csb = sb + (uint32_t)(kt % 3) * AS_STAGE_B;
#pragma unroll
        for (int kk = 0; kk < 32; kk += 16) {
            uint32_t ah[2][4], al[2][4];
#pragma unroll
            for (int fm = 0; fm < 2; ++fm) {
                int rowb = wm * 32 + fm * 16 + a_mrow;
                uint32_t sw = (uint32_t)(((kk >> 3) + a_ch) ^ ((rowb >> 1) & 3));
                uint32_t ad = csb + rowb * 64 + (sw << 4);
                ldsm4(ah[fm][0], ah[fm][1], ah[fm][2], ah[fm][3], ad);
                ldsm4(al[fm][0], al[fm][1], al[fm][2], al[fm][3], ad + 8192);
            }
#pragma unroll
            for (int fnp = 0; fnp < 4; ++fnp) {
                uint32_t bh[4], bl[4];
                int nrow = wn * 64 + fnp * 16 + b_nrow;
                uint32_t sw = (uint32_t)(((kk >> 3) + b_ch) ^ ((nrow >> 1) & 3));
                uint32_t bd = csb + 16384 + nrow * 64 + (sw << 4);
                ldsm4(bh[0], bh[1], bh[2], bh[3], bd);
                ldsm4(bl[0], bl[1], bl[2], bl[3], bd + 8192);
#pragma unroll
                for (int fm = 0; fm < 2; ++fm) {
                    float *d0 = acc[fm][fnp * 2];
                    float *d1 = acc[fm][fnp * 2 + 1];
                    MMA16816(d0, ah[fm][0], ah[fm][1], ah[fm][2], ah[fm][3], bh[0], bh[1]);
                    MMA16816(d0, ah[fm][0], ah[fm][1], ah[fm][2], ah[fm][3], bl[0], bl[1]);
                    MMA16816(d0, al[fm][0], al[fm][1], al[fm][2], al[fm][3], bh[0], bh[1]);
                    MMA16816(d1, ah[fm][0], ah[fm][1], ah[fm][2], ah[fm][3], bh[2], bh[3]);
                    MMA16816(d1, ah[fm][0], ah[fm][1], ah[fm][2], ah[fm][3], bl[2], bl[3]);
                    MMA16816(d1, al[fm][0], al[fm][1], al[fm][2], al[fm][3], bh[2], bh[3]);
                }
            }
        }
    }
    __syncthreads();

    const float *h0p = g_hW4[0] + (size_t)b * CH;
    const float *h1p = g_hW4[1] + (size_t)b * CH;
    const float *h2p = g_hW4[2] + (size_t)b * CH;
    const float *h3p = g_hW4[3] + (size_t)b * CH;
    float pA[2] = {0.f, 0.f}, pB[2] = {0.f, 0.f};
#pragma unroll
    for (int fm = 0; fm < 2; ++fm)
#pragma unroll
        for (int fn = 0; fn < 8; ++fn) {
            int col = n0 + wn * 64 + fn * 8 + (t4 << 1);
            float hw0 = h0p[col] + h1p[col] + h2p[col] + h3p[col] + attn_b[col];
            float hw1 = h0p[col + 1] + h1p[col + 1] + h2p[col + 1] +
                        h3p[col + 1] + attn_b[col + 1];
            float v0 = v[col], v1 = v[col + 1];
            pA[fm] += tanhf(acc[fm][fn][0] + hw0) * v0 +
                      tanhf(acc[fm][fn][1] + hw1) * v1;
            pB[fm] += tanhf(acc[fm][fn][2] + hw0) * v0 +
                      tanhf(acc[fm][fn][3] + hw1) * v1;
        }
#pragma unroll
    for (int fm = 0; fm < 2; ++fm)
#pragma unroll
        for (int j = 0; j < 2; ++j) {
            float val = j ? pB[fm] : pA[fm];
            val += __shfl_xor_sync(0xffffffffu, val, 1);
            val += __shfl_xor_sync(0xffffffffu, val, 2);
            if (t4 == 0) atomicAdd(&red[wm * 32 + fm * 16 + j * 8 + gid], val);
        }
    __syncthreads();
    if (tid < 128) atomicAdd(&g_score[b * 128 + tid], red[tid]);
}

// ---------------- context (+inline softmax) + assemble xin -------------------
// grid (128, 4). 16-deep explicit prefetch of enc (MLP; 8-deep measured 52% DRAM).
__global__ __launch_bounds__(256) void context_kernel(
    const int *__restrict__ x, const float *__restrict__ emb_table,
    const float *__restrict__ hidden, const float *__restrict__ enc,
    float *__restrict__ out_attn) {
    const int b = blockIdx.x;
    const int q = blockIdx.y;
    const int t = threadIdx.x;
    __shared__ float w_s[128];
    __shared__ float r_s[128];
    if (t < 128) {
        float s = g_score[b * 128 + t];
        w_s[t] = s;
        r_s[t] = s;
    }
    __syncthreads();
#pragma unroll
    for (int st = 64; st > 0; st >>= 1) {
        if (t < st) r_s[t] = fmaxf(r_s[t], r_s[t + st]);
        __syncthreads();
    }
    float mx = r_s[0];
    __syncthreads();
    if (t < 128) r_s[t] = expf(w_s[t] - mx);
    __syncthreads();
    float e_t = (t < 128) ? r_s[t] : 0.f;
#pragma unroll
    for (int st = 64; st > 0; st >>= 1) {
        if (t < st) r_s[t] += r_s[t + st];
        __syncthreads();
    }
    float inv = 1.0f / r_s[0];
    __syncthreads();
    if (t < 128) {
        float w = e_t * inv;
        w_s[t] = w;
        if (q == 0) out_attn[b * 128 + t] = w;
    }

    const int h = q * 256 + t;
    if (q < 2) {
        int i = q * 256 + t;
        __nv_bfloat16 hi, lo;
        splitf(emb_table[(size_t)x[b] * CE + i], hi, lo);
        g_xin_hi[(size_t)b * 2560 + i] = hi;
        g_xin_lo[(size_t)b * 2560 + i] = lo;
    }
    {
        __nv_bfloat16 hi, lo;
        splitf(hidden[(size_t)b * CH + h], hi, lo);
        g_xin_hi[(size_t)b * 2560 + 1536 + h] = hi;
        g_xin_lo[(size_t)b * 2560 + 1536 + h] = lo;
    }
    __syncthreads();

    const float *encb = enc + (size_t)b * CS * CH + h;
    float acc = 0.f;
    float vbuf[16];
#pragma unroll
    for (int i = 0; i < 16; ++i) vbuf[i] = __ldcs(encb + (size_t)i * CH);
    for (int s0 = 0; s0 < CS; s0 += 16) {
        float cur[16];
#pragma unroll
        for (int i = 0; i < 16; ++i) cur[i] = vbuf[i];
        if (s0 + 16 < CS) {
#pragma unroll
            for (int i = 0; i < 16; ++i)
                vbuf[i] = __ldcs(encb + (size_t)(s0 + 16 + i) * CH);
        }
#pragma unroll
        for (int i = 0; i < 16; ++i) acc += w_s[s0 + i] * cur[i];
    }

    __nv_bfloat16 hi, lo;
    splitf(acc, hi, lo);
    g_xin_hi[(size_t)b * 2560 + 512 + h] = hi;
    g_xin_lo[(size_t)b * 2560 + 512 + h] = lo;
    g_out2_hi[(size_t)b * 2048 + 1024 + h] = hi;
    g_out2_lo[(size_t)b * 2048 + 1024 + h] = lo;
}

// ---------------- LSTM pointwise ---------------------------------------------
__global__ __launch_bounds__(256) void lstm_kernel(
    const float *__restrict__ cell, float *__restrict__ out_h,
    float *__restrict__ out_c) {
    int id = blockIdx.x * 256 + threadIdx.x;
    int b = id >> 10;
    int h = id & 1023;
    const float *gt = g_gates + (size_t)b * 4096;
    float gi = gt[h], gf = gt[1024 + h], gg = gt[2048 + h], go = gt[3072 + h];
    float c_old = cell[(size_t)b * CH + h];
    float cn = sigf(gf) * c_old + sigf(gi) * tanhf(gg);
    float hn = sigf(go) * tanhf(cn);
    out_h[(size_t)b * CH + h] = hn;
    out_c[(size_t)b * CH + h] = cn;
    __nv_bfloat16 hi, lo;
    splitf(hn, hi, lo);
    g_out2_hi[(size_t)b * 2048 + h] = hi;
    g_out2_lo[(size_t)b * 2048 + h] = lo;
}

// ---------------- launch ------------------------------------------------------
extern "C" void kernel_launch(void *const *d_in, const int *in_sizes, int n_in,
                              void *d_out, int out_size) {
    (void)in_sizes; (void)n_in; (void)out_size;
    const int *x           = (const int *)d_in[0];
    const float *hidden    = (const float *)d_in[1];
    const float *cell      = (const float *)d_in[2];
    const float *enc       = (const float *)d_in[3];
    const float *emb_table = (const float *)d_in[4];
    const float *attn_W    = (const float *)d_in[5];
    const float *attn_b    = (const float *)d_in[6];
    const float *v         = (const float *)d_in[7];
    const float *W_ih      = (const float *)d_in[8];
    const float *W_hh      = (const float *)d_in[9];
    const float *b_ih      = (const float *)d_in[10];
    const float *b_hh      = (const float *)d_in[11];
    const float *fc_W      = (const float *)d_in[12];
    const float *fc_b      = (const float *)d_in[13];

    float *out        = (float *)d_out;
    float *out_logits = out;
    float *out_h      = out + (size_t)CB * CV;
    float *out_c      = out_h + (size_t)CB * CH;
    float *out_attn   = out_c + (size_t)CB * CH;

    float *gatesp = nullptr;
    __nv_bfloat16 *o2h = nullptr, *o2l = nullptr, *xih = nullptr, *xil = nullptr;
    cudaGetSymbolAddress((void **)&gatesp, g_gates);
    cudaGetSymbolAddress((void **)&o2h, g_out2_hi);
    cudaGetSymbolAddress((void **)&o2l, g_out2_lo);
    cudaGetSymbolAddress((void **)&xih, g_xin_hi);
    cudaGetSymbolAddress((void **)&xil, g_xin_lo);

    cudaFuncSetAttribute(attn_score_kernel,
                         cudaFuncAttributeMaxDynamicSharedMemorySize,
                         ATTN_SMEM_BYTES);
    cudaFuncSetAttribute(gemm2_kernel,
                         cudaFuncAttributeMaxDynamicSharedMemorySize,
                         G2_SMEM_BYTES);
    cudaFuncSetAttribute(fc_kernel,
                         cudaFuncAttributeMaxDynamicSharedMemorySize,
                         FC_SMEM_BYTES);

    // 1) merged: hw GEMM (first 256 blocks, overlapped) + splits + init
    conv_hw_kernel<<<16384 + 256, 256>>>(enc, attn_W, b_ih, b_hh, hidden);
    // 2) fused energy GEMM + tanh + v-dot -> raw g_score
    attn_score_kernel<<<dim3(8, CB), 256, ATTN_SMEM_BYTES>>>(v, attn_b);
    // 3) context (+inline softmax) + xin assembly
    context_kernel<<<dim3(CB, 4), 256>>>(x, emb_table, hidden, enc, out_attn);
    // 4) gates += xin @ [W_ih|W_hh]^T  (single launch, K-split via grid.y)
    gemm2_kernel<<<dim3(4096 / 64, 4), 256, G2_SMEM_BYTES>>>(
        xih, xil, 2560,
        W_ih, 1536, 1536, W_hh, CH,
        nullptr, gatesp, 4096, 640, 1);
    // 5) LSTM pointwise
    lstm_kernel<<<(CB * CH) / 256, 256>>>(cell, out_h, out_c);
    // 6) logits = [h_new|context] @ fc_W^T + fc_b
    fc_kernel<<<CV / 128, 256, FC_SMEM_BYTES>>>(o2h, o2l, fc_W, fc_b, out_logits);
}

// round 15
// speedup vs baseline: 1.1089x; 1.0026x over previous
#include <cuda_runtime.h>
#include <cuda_bf16.h>
#include <stdint.h>
#include <math.h>

#define CB 128
#define CS 128
#define CH 1024
#define CE 512
#define CV 32000

// ---------------- scratch (__device__ globals; no allocations allowed) -------
__device__ __align__(16) float g_hW4[4][CB * CH];  // per-K-chunk partials of hW
__device__ __align__(16) float g_score[CB * CS];   // raw scores
__device__ __align__(16) float g_gates[CB * 4096];
__device__ __align__(16) __nv_bfloat16 g_xin_hi[CB * 2560];   // [emb|context|h_last]
__device__ __align__(16) __nv_bfloat16 g_xin_lo[CB * 2560];
__device__ __align__(16) __nv_bfloat16 g_out2_hi[CB * 2048];  // [h_new | context]
__device__ __align__(16) __nv_bfloat16 g_out2_lo[CB * 2048];
__device__ __align__(16) __nv_bfloat16 g_enc_hi[CB * CS * CH];
__device__ __align__(16) __nv_bfloat16 g_enc_lo[CB * CS * CH];
__device__ __align__(16) __nv_bfloat16 g_w2_hi[CH * CH];      // attn_W[:, H:2H] as [n][k]
__device__ __align__(16) __nv_bfloat16 g_w2_lo[CH * CH];

// ---------------- helpers ----------------------------------------------------
__device__ __forceinline__ void splitf(float x, __nv_bfloat16 &hi, __nv_bfloat16 &lo) {
    hi = __float2bfloat16_rn(x);
    lo = __float2bfloat16_rn(x - __bfloat162float(hi));
}
__device__ __forceinline__ float sigf(float x) { return 1.0f / (1.0f + expf(-x)); }
__device__ __forceinline__ uint32_t s2u(const void *p) {
    return (uint32_t)__cvta_generic_to_shared(p);
}
__device__ __forceinline__ void ldsm4(uint32_t &r0, uint32_t &r1, uint32_t &r2,
                                      uint32_t &r3, uint32_t addr) {
    asm volatile("ldmatrix.sync.aligned.m8n8.x4.shared.b16 {%0,%1,%2,%3}, [%4];"
                 : "=r"(r0), "=r"(r1), "=r"(r2), "=r"(r3)
                 : "r"(addr));
}

#define MMA16816(d, a0, a1, a2, a3, b0, b1)                                    \
    asm volatile(                                                              \
        "mma.sync.aligned.m16n8k16.row.col.f32.bf16.bf16.f32 "                 \
        "{%0,%1,%2,%3},{%4,%5,%6,%7},{%8,%9},{%0,%1,%2,%3};\n"                 \
        : "+f"(d[0]), "+f"(d[1]), "+f"(d[2]), "+f"(d[3])                       \
        : "r"(a0), "r"(a1), "r"(a2), "r"(a3), "r"(b0), "r"(b1))

#define CPASYNC16(dst, src)                                                    \
    asm volatile("cp.async.cg.shared.global [%0], [%1], 16;\n" ::"r"(dst),     \
                 "l"(src))
#define CPCOMMIT asm volatile("cp.async.commit_group;\n" ::)
#define CPWAIT1 asm volatile("cp.async.wait_group 1;\n" ::)
#define CPWAIT0 asm volatile("cp.async.wait_group 0;\n" ::)

// ---------------- merged: hw GEMM (blocks 0..255) + splits/init --------------
__global__ __launch_bounds__(256) void conv_hw_kernel(
    const float *__restrict__ enc, const float *__restrict__ attn_W,
    const float *__restrict__ b_ih, const float *__restrict__ b_hh,
    const float *__restrict__ hidden) {
    __shared__ float Hs[128][65];
    __shared__ float Ws[16][65];
    const int tid = threadIdx.x;

    if (blockIdx.x < 256) {
        const int n0 = (blockIdx.x & 63) * 16;
        const int kq = blockIdx.x >> 6;
        const int kbase = kq * 256;
        const int bt = tid & 63;
        const int nt = tid >> 6;
        float acc[2][4] = {{0.f, 0.f, 0.f, 0.f}, {0.f, 0.f, 0.f, 0.f}};

        for (int kc = 0; kc < 4; ++kc) {
            const int k0 = kbase + kc * 64;
#pragma unroll
            for (int i = 0; i < 8; ++i) {
                int idx = tid + 256 * i;
                int row = idx >> 4;
                int cv = (idx & 15) << 2;
                float4 v4 = *(const float4 *)(hidden + (size_t)row * CH + k0 + cv);
                Hs[row][cv] = v4.x; Hs[row][cv + 1] = v4.y;
                Hs[row][cv + 2] = v4.z; Hs[row][cv + 3] = v4.w;
            }
            {
                int row = tid >> 4;
                int cv = (tid & 15) << 2;
                float4 v4 = *(const float4 *)(attn_W + (size_t)(n0 + row) * 2048 + k0 + cv);
                Ws[row][cv] = v4.x; Ws[row][cv + 1] = v4.y;
                Ws[row][cv + 2] = v4.z; Ws[row][cv + 3] = v4.w;
            }
            __syncthreads();
#pragma unroll 8
            for (int k = 0; k < 64; ++k) {
                float w0 = Ws[nt * 4 + 0][k], w1 = Ws[nt * 4 + 1][k];
                float w2 = Ws[nt * 4 + 2][k], w3 = Ws[nt * 4 + 3][k];
                float h0 = Hs[bt * 2 + 0][k], h1 = Hs[bt * 2 + 1][k];
                acc[0][0] += h0 * w0; acc[0][1] += h0 * w1;
                acc[0][2] += h0 * w2; acc[0][3] += h0 * w3;
                acc[1][0] += h1 * w0; acc[1][1] += h1 * w1;
                acc[1][2] += h1 * w2; acc[1][3] += h1 * w3;
            }
            __syncthreads();
        }
#pragma unroll
        for (int i = 0; i < 2; ++i)
#pragma unroll
            for (int j = 0; j < 4; ++j) {
                int n = n0 + nt * 4 + j;
                g_hW4[kq][(size_t)(bt * 2 + i) * CH + n] = acc[i][j];
            }
        return;
    }

    const int cx = blockIdx.x - 256;  // 0..16383
    size_t idx = (size_t)cx * 256 + tid;
    float4 v4 = ((const float4 *)enc)[idx];
    __nv_bfloat16 h0, h1, h2, h3, l0, l1, l2, l3;
    splitf(v4.x, h0, l0); splitf(v4.y, h1, l1);
    splitf(v4.z, h2, l2); splitf(v4.w, h3, l3);
    ((__nv_bfloat162 *)g_enc_hi)[idx * 2 + 0] = __halves2bfloat162(h0, h1);
    ((__nv_bfloat162 *)g_enc_hi)[idx * 2 + 1] = __halves2bfloat162(h2, h3);
    ((__nv_bfloat162 *)g_enc_lo)[idx * 2 + 0] = __halves2bfloat162(l0, l1);
    ((__nv_bfloat162 *)g_enc_lo)[idx * 2 + 1] = __halves2bfloat162(l2, l3);

    if (cx >= 1024) return;
    if (cx < 64) g_score[cx * 256 + tid] = 0.f;
    {
        int i2 = (cx * 256 + tid) * 2;
        g_gates[i2]     = b_ih[i2 & 4095] + b_hh[i2 & 4095];
        g_gates[i2 + 1] = b_ih[(i2 + 1) & 4095] + b_hh[(i2 + 1) & 4095];
    }
    size_t idx2 = (size_t)cx * 256 + tid;
    int n = (int)(idx2 >> 8);
    int k = (int)(idx2 & 255) << 2;
    float4 w4 = *(const float4 *)(attn_W + (size_t)n * 2048 + 1024 + k);
    splitf(w4.x, h0, l0); splitf(w4.y, h1, l1);
    splitf(w4.z, h2, l2); splitf(w4.w, h3, l3);
    size_t o = ((size_t)n * CH + k) >> 1;
    ((__nv_bfloat162 *)g_w2_hi)[o + 0] = __halves2bfloat162(h0, h1);
    ((__nv_bfloat162 *)g_w2_hi)[o + 1] = __halves2bfloat162(h2, h3);
    ((__nv_bfloat162 *)g_w2_lo)[o + 0] = __halves2bfloat162(l0, l1);
    ((__nv_bfloat162 *)g_w2_lo)[o + 1] = __halves2bfloat162(l2, l3);
}

// ---------------- gates GEMM: 128-wide fc-style tile, K-split x8, atomic -----
// C[128,4096] += xin @ [W_ih|W_hh]^T. grid (32, 8): x = n-tile of 128,
// y = K-chunk of 320 (10 k-tiles). Swizzled 64B rows, 3-stage, one barrier.
#define GT_STAGE_B 32768
#define GT_SMEM_BYTES (3 * GT_STAGE_B)

__global__ __launch_bounds__(256, 2) void gates128_kernel(
    const __nv_bfloat16 *__restrict__ Ahi, const __nv_bfloat16 *__restrict__ Alo,
    const float *__restrict__ B1, const float *__restrict__ B2,
    float *__restrict__ C) {
    extern __shared__ __align__(16) char smem[];
    const uint32_t sb = s2u(smem);

    const int tid = threadIdx.x;
    const int lane = tid & 31;
    const int gid = lane >> 2;
    const int t4 = lane & 3;
    const int wm = (tid >> 5) >> 1;
    const int wn = (tid >> 5) & 1;
    const int n0 = blockIdx.x * 128;
    const int kbase = blockIdx.y * 320;

    const int a_mrow = (lane & 15);
    const int a_ch = lane >> 4;
    const int b_nrow = (lane & 7) + ((lane >> 4) << 3);
    const int b_ch = (lane >> 3) & 1;

    float acc[2][8][4];
#pragma unroll
    for (int i = 0; i < 2; i++)
#pragma unroll
        for (int j = 0; j < 8; j++)
#pragma unroll
            for (int c = 0; c < 4; c++) acc[i][j][c] = 0.f;

    float4 breg[4];
    auto ldB = [&](int k0) {
#pragma unroll
        for (int i = 0; i < 4; ++i) {
            int idx = tid + i * 256;
            int row = n0 + (idx >> 3);
            int k = kbase + k0 + ((idx & 7) << 2);
            const float *src = (k < 1536) ? (B1 + (size_t)row * 1536 + k)
                                          : (B2 + (size_t)row * CH + (k - 1536));
            breg[i] = *(const float4 *)src;
        }
    };
    auto stB = [&](int st) {
#pragma unroll
        for (int i = 0; i < 4; ++i) {
            int idx = tid + i * 256;
            int row = idx >> 3;
            int colf = (idx & 7) << 2;
            int boff = colf * 2;
            int ch = boff >> 4;
            int inner = boff & 15;
            uint32_t off = (uint32_t)st * GT_STAGE_B + 16384 + row * 64 +
                           ((uint32_t)(ch ^ ((row >> 1) & 3)) << 4) + inner;
            __nv_bfloat16 h0, h1, h2, h3, l0, l1, l2, l3;
            splitf(breg[i].x, h0, l0); splitf(breg[i].y, h1, l1);
            splitf(breg[i].z, h2, l2); splitf(breg[i].w, h3, l3);
            *(__nv_bfloat162 *)(smem + off)        = __halves2bfloat162(h0, h1);
            *(__nv_bfloat162 *)(smem + off + 4)    = __halves2bfloat162(h2, h3);
            *(__nv_bfloat162 *)(smem + off + 8192) = __halves2bfloat162(l0, l1);
            *(__nv_bfloat162 *)(smem + off + 8196) = __halves2bfloat162(l2, l3);
        }
    };
    auto cpA = [&](int st, int k0) {
#pragma unroll
        for (int i = 0; i < 2; ++i) {
            int idx = tid + i * 256;
            int row = idx >> 2;
            int ch = idx & 3;
            uint32_t so = (uint32_t)st * GT_STAGE_B + row * 64 +
                          ((uint32_t)(ch ^ ((row >> 1) & 3)) << 4);
            size_t go = (size_t)row * 2560 + kbase + k0 + ch * 8;
            CPASYNC16(sb + so, Ahi + go);
            CPASYNC16(sb + 8192 + so, Alo + go);
        }
        CPCOMMIT;
    };

    cpA(0, 0);
    cpA(1, 32);
    ldB(0);
    stB(0);
    ldB(32);

    const int nk = 10;
    for (int kt = 0; kt < nk; ++kt) {
        if (kt < nk - 1) { CPWAIT1; } else { CPWAIT0; }
        __syncthreads();
        if (kt + 1 < nk) stB((kt + 1) % 3);
        if (kt + 2 < nk) {
            ldB((kt + 2) * 32);
            cpA((kt + 2) % 3, (kt + 2) * 32);
        }
        const uint32_t csb = sb + (uint32_t)(kt % 3) * GT_STAGE_B;
#pragma unroll
        for (int kk = 0; kk < 32; kk += 16) {
            uint32_t ah[2][4], al[2][4];
#pragma unroll
            for (int fm = 0; fm < 2; ++fm) {
                int rowb = wm * 32 + fm * 16 + a_mrow;
                uint32_t sw = (uint32_t)(((kk >> 3) + a_ch) ^ ((rowb >> 1) & 3));
                uint32_t ad = csb + rowb * 64 + (sw << 4);
                ldsm4(ah[fm][0], ah[fm][1], ah[fm][2], ah[fm][3], ad);
                ldsm4(al[fm][0], al[fm][1], al[fm][2], al[fm][3], ad + 8192);
            }
#pragma unroll
            for (int fnp = 0; fnp < 4; ++fnp) {
                uint32_t bh[4], bl[4];
                int nrow = wn * 64 + fnp * 16 + b_nrow;
                uint32_t sw = (uint32_t)(((kk >> 3) + b_ch) ^ ((nrow >> 1) & 3));
                uint32_t bd = csb + 16384 + nrow * 64 + (sw << 4);
                ldsm4(bh[0], bh[1], bh[2], bh[3], bd);
                ldsm4(bl[0], bl[1], bl[2], bl[3], bd + 8192);
#pragma unroll
                for (int fm = 0; fm < 2; ++fm) {
                    float *d0 = acc[fm][fnp * 2];
                    float *d1 = acc[fm][fnp * 2 + 1];
                    MMA16816(d0, ah[fm][0], ah[fm][1], ah[fm][2], ah[fm][3], bh[0], bh[1]);
                    MMA16816(d0, ah[fm][0], ah[fm][1], ah[fm][2], ah[fm][3], bl[0], bl[1]);
                    MMA16816(d0, al[fm][0], al[fm][1], al[fm][2], al[fm][3], bh[0], bh[1]);
                    MMA16816(d1, ah[fm][0], ah[fm][1], ah[fm][2], ah[fm][3], bh[2], bh[3]);
                    MMA16816(d1, ah[fm][0], ah[fm][1], ah[fm][2], ah[fm][3], bl[2], bl[3]);
                    MMA16816(d1, al[fm][0], al[fm][1], al[fm][2], al[fm][3], bh[2], bh[3]);
                }
            }
        }
    }
#pragma unroll
    for (int fm = 0; fm < 2; ++fm)
#pragma unroll
        for (int fn = 0; fn < 8; ++fn) {
            int row = wm * 32 + fm * 16 + gid;
            int col = n0 + wn * 64 + fn * 8 + (t4 << 1);
            atomicAdd(&C[(size_t)row * 4096 + col], acc[fm][fn][0]);
            atomicAdd(&C[(size_t)row * 4096 + col + 1], acc[fm][fn][1]);
            atomicAdd(&C[(size_t)(row + 8) * 4096 + col], acc[fm][fn][2]);
            atomicAdd(&C[(size_t)(row + 8) * 4096 + col + 1], acc[fm][fn][3]);
        }
}

// ---------------- FC GEMM: logits = out2 @ fc_W^T + fc_b ---------------------
#define FC_STAGE_B 32768
#define FC_SMEM_BYTES (3 * FC_STAGE_B)

__global__ __launch_bounds__(256, 2) void fc_kernel(
    const __nv_bfloat16 *__restrict__ Ahi, const __nv_bfloat16 *__restrict__ Alo,
    const float *__restrict__ B, const float *__restrict__ bias,
    float *__restrict__ C) {
    extern __shared__ __align__(16) char smem[];
    const uint32_t sb = s2u(smem);

    const int tid = threadIdx.x;
    const int lane = tid & 31;
    const int gid = lane >> 2;
    const int t4 = lane & 3;
    const int wm = (tid >> 5) >> 1;
    const int wn = (tid >> 5) & 1;
    const int n0 = blockIdx.x * 128;

    const int a_mrow = (lane & 15);
    const int a_ch = lane >> 4;
    const int b_nrow = (lane & 7) + ((lane >> 4) << 3);
    const int b_ch = (lane >> 3) & 1;

    float acc[2][8][4];
#pragma unroll
    for (int i = 0; i < 2; i++)
#pragma unroll
        for (int j = 0; j < 8; j++)
#pragma unroll
            for (int c = 0; c < 4; c++) acc[i][j][c] = 0.f;

    float4 breg[4];
    auto ldB = [&](int k0) {
#pragma unroll
        for (int i = 0; i < 4; ++i) {
            int idx = tid + i * 256;
            int row = n0 + (idx >> 3);
            int col = (idx & 7) << 2;
            breg[i] = *(const float4 *)(B + (size_t)row * 2048 + k0 + col);
        }
    };
    auto stB = [&](int st) {
#pragma unroll
        for (int i = 0; i < 4; ++i) {
            int idx = tid + i * 256;
            int row = idx >> 3;
            int colf = (idx & 7) << 2;
            int boff = colf * 2;
            int ch = boff >> 4;
            int inner = boff & 15;
            uint32_t off = (uint32_t)st * FC_STAGE_B + 16384 + row * 64 +
                           ((uint32_t)(ch ^ ((row >> 1) & 3)) << 4) + inner;
            __nv_bfloat16 h0, h1, h2, h3, l0, l1, l2, l3;
            splitf(breg[i].x, h0, l0); splitf(breg[i].y, h1, l1);
            splitf(breg[i].z, h2, l2); splitf(breg[i].w, h3, l3);
            *(__nv_bfloat162 *)(smem + off)        = __halves2bfloat162(h0, h1);
            *(__nv_bfloat162 *)(smem + off + 4)    = __halves2bfloat162(h2, h3);
            *(__nv_bfloat162 *)(smem + off + 8192) = __halves2bfloat162(l0, l1);
            *(__nv_bfloat162 *)(smem + off + 8196) = __halves2bfloat162(l2, l3);
        }
    };
    auto cpA = [&](int st, int k0) {
#pragma unroll
        for (int i = 0; i < 2; ++i) {
            int idx = tid + i * 256;
            int row = idx >> 2;
            int ch = idx & 3;
            uint32_t so = (uint32_t)st * FC_STAGE_B + row * 64 +
                          ((uint32_t)(ch ^ ((row >> 1) & 3)) << 4);
            size_t go = (size_t)row * 2048 + k0 + ch * 8;
            CPASYNC16(sb + so, Ahi + go);
            CPASYNC16(sb + 8192 + so, Alo + go);
        }
        CPCOMMIT;
    };

    cpA(0, 0);
    cpA(1, 32);
    ldB(0);
    stB(0);
    ldB(32);

    const int nk = 2048 / 32;
    for (int kt = 0; kt < nk; ++kt) {
        if (kt < nk - 1) { CPWAIT1; } else { CPWAIT0; }
        __syncthreads();
        if (kt + 1 < nk) stB((kt + 1) % 3);
        if (kt + 2 < nk) {
            ldB((kt + 2) * 32);
            cpA((kt + 2) % 3, (kt + 2) * 32);
        }
        const uint32_t csb = sb + (uint32_t)(kt % 3) * FC_STAGE_B;
#pragma unroll
        for (int kk = 0; kk < 32; kk += 16) {
            uint32_t ah[2][4], al[2][4];
#pragma unroll
            for (int fm = 0; fm < 2; ++fm) {
                int rowb = wm * 32 + fm * 16 + a_mrow;
                uint32_t sw = (uint32_t)(((kk >> 3) + a_ch) ^ ((rowb >> 1) & 3));
                uint32_t ad = csb + rowb * 64 + (sw << 4);
                ldsm4(ah[fm][0], ah[fm][1], ah[fm][2], ah[fm][3], ad);
                ldsm4(al[fm][0], al[fm][1], al[fm][2], al[fm][3], ad + 8192);
            }
#pragma unroll
            for (int fnp = 0; fnp < 4; ++fnp) {
                uint32_t bh[4], bl[4];
                int nrow = wn * 64 + fnp * 16 + b_nrow;
                uint32_t sw = (uint32_t)(((kk >> 3) + b_ch) ^ ((nrow >> 1) & 3));
                uint32_t bd = csb + 16384 + nrow * 64 + (sw << 4);
                ldsm4(bh[0], bh[1], bh[2], bh[3], bd);
                ldsm4(bl[0], bl[1], bl[2], bl[3], bd + 8192);
#pragma unroll
                for (int fm = 0; fm < 2; ++fm) {
                    float *d0 = acc[fm][fnp * 2];
                    float *d1 = acc[fm][fnp * 2 + 1];
                    MMA16816(d0, ah[fm][0], ah[fm][1], ah[fm][2], ah[fm][3], bh[0], bh[1]);
                    MMA16816(d0, ah[fm][0], ah[fm][1], ah[fm][2], ah[fm][3], bl[0], bl[1]);
                    MMA16816(d0, al[fm][0], al[fm][1], al[fm][2], al[fm][3], bh[0], bh[1]);
                    MMA16816(d1, ah[fm][0], ah[fm][1], ah[fm][2], ah[fm][3], bh[2], bh[3]);
                    MMA16816(d1, ah[fm][0], ah[fm][1], ah[fm][2], ah[fm][3], bl[2], bl[3]);
                    MMA16816(d1, al[fm][0], al[fm][1], al[fm][2], al[fm][3], bh[2], bh[3]);
                }
            }
        }
    }
#pragma unroll
    for (int fm = 0; fm < 2; ++fm)
#pragma unroll
        for (int fn = 0; fn < 8; ++fn) {
            int row = wm * 32 + fm * 16 + gid;
            int col = n0 + wn * 64 + fn * 8 + (t4 << 1);
            float b0 = bias[col], b1 = bias[col + 1];
            C[(size_t)row * CV + col]           = acc[fm][fn][0] + b0;
            C[(size_t)row * CV + col + 1]       = acc[fm][fn][1] + b1;
            C[(size_t)(row + 8) * CV + col]     = acc[fm][fn][2] + b0;
            C[(size_t)(row + 8) * CV + col + 1] = acc[fm][fn][3] + b1;
        }
}

// ---------------- fused energy GEMM + tanh + v-dot -> score[B,S] -------------
#define AS_STAGE_B 32768
#define ATTN_SMEM_BYTES (3 * AS_STAGE_B + 512)

__global__ __launch_bounds__(256, 2) void attn_score_kernel(
    const float *__restrict__ v, const float *__restrict__ attn_b) {
    extern __shared__ __align__(16) char smem[];
    const uint32_t sb = s2u(smem);
    float *red = (float *)(smem + 3 * AS_STAGE_B);

    const int b = blockIdx.y;
    const int n0 = blockIdx.x * 128;
    const int tid = threadIdx.x;
    const int lane = tid & 31;
    const int gid = lane >> 2;
    const int t4 = lane & 3;
    const int wm = (tid >> 5) >> 1;
    const int wn = (tid >> 5) & 1;
    if (tid < 128) red[tid] = 0.f;

    const int a_mrow = (lane & 15);
    const int a_ch = lane >> 4;
    const int b_nrow = (lane & 7) + ((lane >> 4) << 3);
    const int b_ch = (lane >> 3) & 1;

    const int ld_row = tid >> 2;
    const int ld_ch = tid & 3;

    float acc[2][8][4];
#pragma unroll
    for (int i = 0; i < 2; i++)
#pragma unroll
        for (int j = 0; j < 8; j++)
#pragma unroll
            for (int c = 0; c < 4; c++) acc[i][j][c] = 0.f;

#define LOAD_STAGE(st, k0)                                                     \
    do {                                                                       \
        _Pragma("unroll") for (int i = 0; i < 2; ++i) {                        \
            int row = ld_row + i * 64;                                         \
            uint32_t so = (uint32_t)(st) * AS_STAGE_B + row * 64 +             \
                          ((uint32_t)(ld_ch ^ ((row >> 1) & 3)) << 4);         \
            size_t goA = (size_t)(b * 128 + row) * CH + (k0) + ld_ch * 8;      \
            size_t goB = (size_t)(n0 + row) * CH + (k0) + ld_ch * 8;           \
            CPASYNC16(sb + so, g_enc_hi + goA);                                \
            CPASYNC16(sb + 8192 + so, g_enc_lo + goA);                         \
            CPASYNC16(sb + 16384 + so, g_w2_hi + goB);                         \
            CPASYNC16(sb + 24576 + so, g_w2_lo + goB);                         \
        }                                                                      \
        CPCOMMIT;                                                              \
    } while (0)

    LOAD_STAGE(0, 0);
    LOAD_STAGE(1, 32);
    for (int kt = 0; kt < 32; ++kt) {
        if (kt < 31) { CPWAIT1; } else { CPWAIT0; }
        __syncthreads();
        if (kt + 2 < 32) LOAD_STAGE((kt + 2) % 3, (kt + 2) * 32);
        const uint32_t csb = sb + (uint32_t)(kt % 3) * AS_STAGE_B;
#pragma unroll
        for (int kk = 0; kk < 32; kk += 16) {
            uint32_t ah[2][4], al[2][4];
#pragma unroll
            for (int fm = 0; fm < 2; ++fm) {
                int rowb = wm * 32 + fm * 16 + a_mrow;
                uint32_t sw = (uint32_t)(((kk >> 3) + a_ch) ^ ((rowb >> 1) & 3));
                uint32_t ad = csb + rowb * 64 + (sw << 4);
                ldsm4(ah[fm][0], ah[fm][1], ah[fm][2], ah[fm][3], ad);
                ldsm4(al[fm][0], al[fm][1], al[fm][2], al[fm][3], ad + 8192);
            }
#pragma unroll
            for (int fnp = 0; fnp < 4; ++fnp) {
                uint32_t bh[4], bl[4];
                int nrow = wn * 64 + fnp * 16 + b_nrow;
                uint32_t sw = (uint32_t)(((kk >> 3) + b_ch) ^ ((nrow >> 1) & 3));
                uint32_t bd = csb + 16384 + nrow * 64 + (sw << 4);
                ldsm4(bh[0], bh[1], bh[2], bh[3], bd);
                ldsm4(bl[0], bl[1], bl[2], bl[3], bd + 8192);
#pragma unroll
                for (int fm = 0; fm < 2; ++fm) {
                    float *d0 = acc[fm][fnp * 2];
                    float *d1 = acc[fm][fnp * 2 + 1];
                    MMA16816(d0, ah[fm][0], ah[fm][1], ah[fm][2], ah[fm][3], bh[0], bh[1]);
                    MMA16816(d0, ah[fm][0], ah[fm][1], ah[fm][2], ah[fm][3], bl[0], bl[1]);
                    MMA16816(d0, al[fm][0], al[fm][1], al[fm][2], al[fm][3], bh[0], bh[1]);
                    MMA16816(d1, ah[fm][0], ah[fm][1], ah[fm][2], ah[fm][3], bh[2], bh[3]);
                    MMA16816(d1, ah[fm][0], ah[fm][1], ah[fm][2], ah[fm][3], bl[2], bl[3]);
                    MMA16816(d1, al[fm][0], al[fm][1], al[fm][2], al[fm][3], bh[2], bh[3]);
                }
            }
        }
    }
    __syncthreads();

    const float *h0p = g_hW4[0] + (size_t)b * CH;
    const float *h1p = g_hW4[1] + (size_t)b * CH;
    const float *h2p = g_hW4[2] + (size_t)b * CH;
    const float *h3p = g_hW4[3] + (size_t)b * CH;
    float pA[2] = {0.f, 0.f}, pB[2] = {0.f, 0.f};
#pragma unroll
    for (int fm = 0; fm < 2; ++fm)
#pragma unroll
        for (int fn = 0; fn < 8; ++fn) {
            int col = n0 + wn * 64 + fn * 8 + (t4 << 1);
            float hw0 = h0p[col] + h1p[col] + h2p[col] + h3p[col] + attn_b[col];
            float hw1 = h0p[col + 1] + h1p[col + 1] + h2p[col + 1] +
                        h3p[col + 1] + attn_b[col + 1];
            float v0 = v[col], v1 = v[col + 1];
            pA[fm] += tanhf(acc[fm][fn][0] + hw0) * v0 +
                      tanhf(acc[fm][fn][1] + hw1) * v1;
            pB[fm] += tanhf(acc[fm][fn][2] + hw0) * v0 +
                      tanhf(acc[fm][fn][3] + hw1) * v1;
        }
#pragma unroll
    for (int fm = 0; fm < 2; ++fm)
#pragma unroll
        for (int j = 0; j < 2; ++j) {
            float val = j ? pB[fm] : pA[fm];
            val += __shfl_xor_sync(0xffffffffu, val, 1);
            val += __shfl_xor_sync(0xffffffffu, val, 2);
            if (t4 == 0) atomicAdd(&red[wm * 32 + fm * 16 + j * 8 + gid], val);
        }
    __syncthreads();
    if (tid < 128) atomicAdd(&g_score[b * 128 + tid], red[tid]);
}

// ---------------- context (+inline softmax) + assemble xin -------------------
__global__ __launch_bounds__(256) void context_kernel(
    const int *__restrict__ x, const float *__restrict__ emb_table,
    const float *__restrict__ hidden, const float *__restrict__ enc,
    float *__restrict__ out_attn) {
    const int b = blockIdx.x;
    const int q = blockIdx.y;
    const int t = threadIdx.x;
    __shared__ float w_s[128];
    __shared__ float r_s[128];
    if (t < 128) {
        float s = g_score[b * 128 + t];
        w_s[t] = s;
        r_s[t] = s;
    }
    __syncthreads();
#pragma unroll
    for (int st = 64; st > 0; st >>= 1) {
        if (t < st) r_s[t] = fmaxf(r_s[t], r_s[t + st]);
        __syncthreads();
    }
    float mx = r_s[0];
    __syncthreads();
    if (t < 128) r_s[t] = expf(w_s[t] - mx);
    __syncthreads();
    float e_t = (t < 128) ? r_s[t] : 0.f;
#pragma unroll
    for (int st = 64; st > 0; st >>= 1) {
        if (t < st) r_s[t] += r_s[t + st];
        __syncthreads();
    }
    float inv = 1.0f / r_s[0];
    __syncthreads();
    if (t < 128) {
        float w = e_t * inv;
        w_s[t] = w;
        if (q == 0) out_attn[b * 128 + t] = w;
    }

    const int h = q * 256 + t;
    if (q < 2) {
        int i = q * 256 + t;
        __nv_bfloat16 hi, lo;
        splitf(emb_table[(size_t)x[b] * CE + i], hi, lo);
        g_xin_hi[(size_t)b * 2560 + i] = hi;
        g_xin_lo[(size_t)b * 2560 + i] = lo;
    }
    {
        __nv_bfloat16 hi, lo;
        splitf(hidden[(size_t)b * CH + h], hi, lo);
        g_xin_hi[(size_t)b * 2560 + 1536 + h] = hi;
        g_xin_lo[(size_t)b * 2560 + 1536 + h] = lo;
    }
    __syncthreads();

    const float *encb = enc + (size_t)b * CS * CH + h;
    float acc = 0.f;
    float vbuf[16];
#pragma unroll
    for (int i = 0; i < 16; ++i) vbuf[i] = __ldcs(encb + (size_t)i * CH);
    for (int s0 = 0; s0 < CS; s0 += 16) {
        float cur[16];
#pragma unroll
        for (int i = 0; i < 16; ++i) cur[i] = vbuf[i];
        if (s0 + 16 < CS) {
#pragma unroll
            for (int i = 0; i < 16; ++i)
                vbuf[i] = __ldcs(encb + (size_t)(s0 + 16 + i) * CH);
        }
#pragma unroll
        for (int i = 0; i < 16; ++i) acc += w_s[s0 + i] * cur[i];
    }

    __nv_bfloat16 hi, lo;
    splitf(acc, hi, lo);
    g_xin_hi[(size_t)b * 2560 + 512 + h] = hi;
    g_xin_lo[(size_t)b * 2560 + 512 + h] = lo;
    g_out2_hi[(size_t)b * 2048 + 1024 + h] = hi;
    g_out2_lo[(size_t)b * 2048 + 1024 + h] = lo;
}

// ---------------- LSTM pointwise ---------------------------------------------
__global__ __launch_bounds__(256) void lstm_kernel(
    const float *__restrict__ cell, float *__restrict__ out_h,
    float *__restrict__ out_c) {
    int id = blockIdx.x * 256 + threadIdx.x;
    int b = id >> 10;
    int h = id & 1023;
    const float *gt = g_gates + (size_t)b * 4096;
    float gi = gt[h], gf = gt[1024 + h], gg = gt[2048 + h], go = gt[3072 + h];
    float c_old = cell[(size_t)b * CH + h];
    float cn = sigf(gf) * c_old + sigf(gi) * tanhf(gg);
    float hn = sigf(go) * tanhf(cn);
    out_h[(size_t)b * CH + h] = hn;
    out_c[(size_t)b * CH + h] = cn;
    __nv_bfloat16 hi, lo;
    splitf(hn, hi, lo);
    g_out2_hi[(size_t)b * 2048 + h] = hi;
    g_out2_lo[(size_t)b * 2048 + h] = lo;
}

// ---------------- launch ------------------------------------------------------
extern "C" void kernel_launch(void *const *d_in, const int *in_sizes, int n_in,
                              void *d_out, int out_size) {
    (void)in_sizes; (void)n_in; (void)out_size;
    const int *x           = (const int *)d_in[0];
    const float *hidden    = (const float *)d_in[1];
    const float *cell      = (const float *)d_in[2];
    const float *enc       = (const float *)d_in[3];
    const float *emb_table = (const float *)d_in[4];
    const float *attn_W    = (const float *)d_in[5];
    const float *attn_b    = (const float *)d_in[6];
    const float *v         = (const float *)d_in[7];
    const float *W_ih      = (const float *)d_in[8];
    const float *W_hh      = (const float *)d_in[9];
    const float *b_ih      = (const float *)d_in[10];
    const float *b_hh      = (const float *)d_in[11];
    const float *fc_W      = (const float *)d_in[12];
    const float *fc_b      = (const float *)d_in[13];

    float *out        = (float *)d_out;
    float *out_logits = out;
    float *out_h      = out + (size_t)CB * CV;
    float *out_c      = out_h + (size_t)CB * CH;
    float *out_attn   = out_c + (size_t)CB * CH;

    float *gatesp = nullptr;
    __nv_bfloat16 *o2h = nullptr, *o2l = nullptr, *xih = nullptr, *xil = nullptr;
    cudaGetSymbolAddress((void **)&gatesp, g_gates);
    cudaGetSymbolAddress((void **)&o2h, g_out2_hi);
    cudaGetSymbolAddress((void **)&o2l, g_out2_lo);
    cudaGetSymbolAddress((void **)&xih, g_xin_hi);
    cudaGetSymbolAddress((void **)&xil, g_xin_lo);

    cudaFuncSetAttribute(attn_score_kernel,
                         cudaFuncAttributeMaxDynamicSharedMemorySize,
                         ATTN_SMEM_BYTES);
    cudaFuncSetAttribute(gates128_kernel,
                         cudaFuncAttributeMaxDynamicSharedMemorySize,
                         GT_SMEM_BYTES);
    cudaFuncSetAttribute(fc_kernel,
                         cudaFuncAttributeMaxDynamicSharedMemorySize,
                         FC_SMEM_BYTES);

    // 1) merged: hw GEMM (first 256 blocks, overlapped) + splits + init
    conv_hw_kernel<<<16384 + 256, 256>>>(enc, attn_W, b_ih, b_hh, hidden);
    // 2) fused energy GEMM + tanh + v-dot -> raw g_score
    attn_score_kernel<<<dim3(8, CB), 256, ATTN_SMEM_BYTES>>>(v, attn_b);
    // 3) context (+inline softmax) + xin assembly
    context_kernel<<<dim3(CB, 4), 256>>>(x, emb_table, hidden, enc, out_attn);
    // 4) gates += xin @ [W_ih|W_hh]^T  (128-wide tile, K-split x8, atomic)
    gates128_kernel<<<dim3(32, 8), 256, GT_SMEM_BYTES>>>(
        xih, xil, W_ih, W_hh, gatesp);
    // 5) LSTM pointwise
    lstm_kernel<<<(CB * CH) / 256, 256>>>(cell, out_h, out_c);
    // 6) logits = [h_new|context] @ fc_W^T + fc_b
    fc_kernel<<<CV / 128, 256, FC_SMEM_BYTES>>>(o2h, o2l, fc_W, fc_b, out_logits);
}